// round 2
// baseline (speedup 1.0000x reference)
#include <cuda_runtime.h>
#include <cstdint>

#define L_SIZE 65536
#define C_SIZE 32768
#define E_SIZE 262144
#define D 128
#define N_ITERS 4

using ull = unsigned long long;

// ---------------- device scratch (allocation-free: __device__ globals) ----------------
__device__ float g_l_emb[(size_t)L_SIZE * D];
__device__ float g_c_emb[(size_t)C_SIZE * D];
__device__ float g_msg_l[(size_t)L_SIZE * D];   // l2c messages, prescaled by 1/sqrt(deg_l)
__device__ float g_msg_c[(size_t)C_SIZE * D];   // c2l messages, prescaled by 1/sqrt(deg_c)
__device__ float g_l2l[(size_t)L_SIZE * D];
__device__ float g_aggr_l[(size_t)L_SIZE * D];
__device__ float g_aggr_c[(size_t)C_SIZE * D];
__device__ int   g_cnt_l[L_SIZE], g_cnt_c[C_SIZE];
__device__ int   g_off_l[L_SIZE], g_off_c[C_SIZE];
__device__ int   g_cur_l[L_SIZE], g_cur_c[C_SIZE];
__device__ int   g_adj_c[E_SIZE];   // grouped by clause, stores literal index
__device__ int   g_adj_l[E_SIZE];   // grouped by literal, stores clause index
__device__ float g_inv_l[L_SIZE], g_inv_c[C_SIZE];
__device__ int   g_bsum[64];
__device__ int   g_idx64;           // 1 if edge indices are int64, 0 if int32

// ---------------- packed fp32x2 helpers (Blackwell FFMA2) ----------------
__device__ __forceinline__ ull dup2(float s) {
    ull d;
    asm("mov.b64 %0, {%1, %1};" : "=l"(d) : "f"(s));
    return d;
}
__device__ __forceinline__ void ffma2(ull& d, ull a, ull b) {
    asm("fma.rn.f32x2 %0, %1, %2, %0;" : "+l"(d) : "l"(a), "l"(b));
}
__device__ __forceinline__ void unpack2(ull p, float& lo, float& hi) {
    asm("mov.b64 {%0, %1}, %2;" : "=f"(lo), "=f"(hi) : "l"(p));
}

// ---------------- edge-index dtype handling ----------------
__device__ __forceinline__ int eidx(const void* p, int i, int f) {
    if (f) return (int)((const unsigned long long*)p)[i];
    return ((const int*)p)[i];
}

__global__ void k_detect(const unsigned* p) {
    // int64 little-endian values < 2^32 => every odd 32-bit word is 0.
    unsigned v = p[2 * threadIdx.x + 1];
    __shared__ int anynz;
    if (threadIdx.x == 0) anynz = 0;
    __syncthreads();
    unsigned b = __ballot_sync(0xffffffffu, v != 0u);
    if ((threadIdx.x & 31) == 0 && b) atomicExch(&anynz, 1);
    __syncthreads();
    if (threadIdx.x == 0) g_idx64 = (anynz == 0) ? 1 : 0;
}

// ---------------- degree histogram ----------------
__global__ void k_hist(const void* lp, const void* cp) {
    int e = blockIdx.x * blockDim.x + threadIdx.x;
    int f = g_idx64;
    int li = eidx(lp, e, f);
    int ci = eidx(cp, e, f);
    atomicAdd(&g_cnt_l[li], 1);
    atomicAdd(&g_cnt_c[ci], 1);
}

// ---------------- 3-kernel exclusive scan (1024 elems / block) ----------------
__global__ void k_bsum(const int* __restrict__ cnt) {
    __shared__ int sh[256];
    int base = blockIdx.x * 1024 + threadIdx.x;
    int s = 0;
#pragma unroll
    for (int t = 0; t < 4; t++) s += cnt[base + t * 256];
    sh[threadIdx.x] = s;
    __syncthreads();
    for (int o = 128; o > 0; o >>= 1) {
        if (threadIdx.x < o) sh[threadIdx.x] += sh[threadIdx.x + o];
        __syncthreads();
    }
    if (threadIdx.x == 0) g_bsum[blockIdx.x] = sh[0];
}
__global__ void k_scan_base(int G) {
    int run = 0;
    for (int i = 0; i < G; i++) { int v = g_bsum[i]; g_bsum[i] = run; run += v; }
}
__global__ void k_scan_write(const int* __restrict__ cnt, int* __restrict__ off,
                             int* __restrict__ cur) {
    __shared__ int sh[256];
    int tid = threadIdx.x;
    int base4 = blockIdx.x * 1024 + tid * 4;
    int4 v = *(const int4*)(cnt + base4);
    int tsum = v.x + v.y + v.z + v.w;
    sh[tid] = tsum;
    __syncthreads();
    for (int o = 1; o < 256; o <<= 1) {
        int t = (tid >= o) ? sh[tid - o] : 0;
        __syncthreads();
        sh[tid] += t;
        __syncthreads();
    }
    int e = g_bsum[blockIdx.x] + sh[tid] - tsum;
    off[base4 + 0] = e; cur[base4 + 0] = e; e += v.x;
    off[base4 + 1] = e; cur[base4 + 1] = e; e += v.y;
    off[base4 + 2] = e; cur[base4 + 2] = e; e += v.z;
    off[base4 + 3] = e; cur[base4 + 3] = e;
}

// ---------------- CSR fill ----------------
__global__ void k_fill(const void* lp, const void* cp) {
    int e = blockIdx.x * blockDim.x + threadIdx.x;
    int f = g_idx64;
    int li = eidx(lp, e, f);
    int ci = eidx(cp, e, f);
    int pc = atomicAdd(&g_cur_c[ci], 1);
    g_adj_c[pc] = li;
    int pl = atomicAdd(&g_cur_l[li], 1);
    g_adj_l[pl] = ci;
}

// ---------------- 1/sqrt(deg) ----------------
__global__ void k_inv() {
    int i = blockIdx.x * blockDim.x + threadIdx.x;
    if (i < L_SIZE) { int c = g_cnt_l[i]; g_inv_l[i] = c ? rsqrtf((float)c) : 0.0f; }
    if (i < C_SIZE) { int c = g_cnt_c[i]; g_inv_c[i] = c ? rsqrtf((float)c) : 0.0f; }
}

// ---------------- broadcast-init embeddings ----------------
__global__ void k_init(float4* __restrict__ dst, const float4* __restrict__ src, int n4) {
    int i = blockIdx.x * blockDim.x + threadIdx.x;
    if (i < n4) dst[i] = src[i & 31];   // 128 floats = 32 float4 per row
}

// ---------------- SGEMM microkernels (128x128 tile, 8x8/thread, f32x2-packed) ----------
__device__ __forceinline__ void mm8(const float* __restrict__ Ab, const float* __restrict__ Bb,
                                    ull (&acc)[4][8], int rm, int rn) {
#pragma unroll
    for (int k = 0; k < 8; k++) {
        const float* ar = Ab + k * 128 + rm;
        const float* br = Bb + k * 128 + rn;
        ulonglong2 A0 = *(const ulonglong2*)ar;
        ulonglong2 A1 = *(const ulonglong2*)(ar + 4);
        float4 b0 = *(const float4*)br;
        float4 b1 = *(const float4*)(br + 4);
        ull bd[8];
        bd[0] = dup2(b0.x); bd[1] = dup2(b0.y); bd[2] = dup2(b0.z); bd[3] = dup2(b0.w);
        bd[4] = dup2(b1.x); bd[5] = dup2(b1.y); bd[6] = dup2(b1.z); bd[7] = dup2(b1.w);
#pragma unroll
        for (int j = 0; j < 8; j++) {
            ffma2(acc[0][j], A0.x, bd[j]);
            ffma2(acc[1][j], A0.y, bd[j]);
            ffma2(acc[2][j], A1.x, bd[j]);
            ffma2(acc[3][j], A1.y, bd[j]);
        }
    }
}

// phase-2 variant: A read from the resident swizzled hidden tile Hs[k][(blk^k&15)*8+i]
__device__ __forceinline__ void mm8_swz(const float* __restrict__ Hs, int k0,
                                        const float* __restrict__ Bb,
                                        ull (&acc)[4][8], int tm, int rn) {
#pragma unroll
    for (int kk = 0; kk < 8; kk++) {
        int k = k0 + kk;
        const float* ar = Hs + k * 128 + ((tm ^ (k & 15)) << 3);
        const float* br = Bb + kk * 128 + rn;
        ulonglong2 A0 = *(const ulonglong2*)ar;
        ulonglong2 A1 = *(const ulonglong2*)(ar + 4);
        float4 b0 = *(const float4*)br;
        float4 b1 = *(const float4*)(br + 4);
        ull bd[8];
        bd[0] = dup2(b0.x); bd[1] = dup2(b0.y); bd[2] = dup2(b0.z); bd[3] = dup2(b0.w);
        bd[4] = dup2(b1.x); bd[5] = dup2(b1.y); bd[6] = dup2(b1.z); bd[7] = dup2(b1.w);
#pragma unroll
        for (int j = 0; j < 8; j++) {
            ffma2(acc[0][j], A0.x, bd[j]);
            ffma2(acc[1][j], A0.y, bd[j]);
            ffma2(acc[2][j], A1.x, bd[j]);
            ffma2(acc[3][j], A1.y, bd[j]);
        }
    }
}

// ---------------- fused 2-layer MLP: out = (relu(X@W1+b1)@W2+b2) * rowscale ----------------
__global__ __launch_bounds__(256, 2) void k_mlp2(
    const float* __restrict__ X,
    const float* __restrict__ W1, const float* __restrict__ b1,
    const float* __restrict__ W2, const float* __restrict__ b2,
    const float* __restrict__ inv, float* __restrict__ out, int swap) {
    extern __shared__ float sm[];
    float* As = sm;          // [2][8][128]
    float* Bs = sm + 2048;   // [2][8][128]
    float* Hs = sm + 4096;   // [128][128] k-major, 8-float-block xor swizzle

    const int tid = threadIdx.x;
    const int tm = tid >> 4, tn = tid & 15;
    const int rm = tm << 3, rn = tn << 3;
    const size_t rowbase = (size_t)blockIdx.x * 128;
    const int lm = tid >> 1;
    const int lq = (tid & 1) << 2;
    const int srow = swap ? (lm ^ 1) : lm;
    const float* Xrow = X + (rowbase + srow) * D + lq;

    ull acc[4][8];
#pragma unroll
    for (int p = 0; p < 4; p++)
#pragma unroll
        for (int j = 0; j < 8; j++) acc[p][j] = 0ull;

    // ---- phase 1: H = relu(X@W1 + b1) ----
    float4 av = *(const float4*)Xrow;
    float4 bv = ((const float4*)W1)[tid];
    {
        float* a0 = As + lq * 128 + lm;
        a0[0] = av.x; a0[128] = av.y; a0[256] = av.z; a0[384] = av.w;
        ((float4*)Bs)[tid] = bv;
    }
    __syncthreads();
#pragma unroll 1
    for (int c = 0; c < 16; c++) {
        int cur = c & 1;
        if (c < 15) {
            av = *(const float4*)(Xrow + (c + 1) * 8);
            bv = ((const float4*)(W1 + (size_t)(c + 1) * 1024))[tid];
        }
        mm8(As + cur * 1024, Bs + cur * 1024, acc, rm, rn);
        if (c < 15) {
            float* a0 = As + (cur ^ 1) * 1024 + lq * 128 + lm;
            a0[0] = av.x; a0[128] = av.y; a0[256] = av.z; a0[384] = av.w;
            ((float4*)(Bs + (cur ^ 1) * 1024))[tid] = bv;
        }
        __syncthreads();
    }
    // epilogue 1: bias + relu, store to swizzled Hs (k-major)
    float b1v[8];
    *(float4*)&b1v[0] = *(const float4*)(b1 + rn);
    *(float4*)&b1v[4] = *(const float4*)(b1 + rn + 4);
#pragma unroll
    for (int j = 0; j < 8; j++) {
        int k = rn + j;
        float h[8];
#pragma unroll
        for (int p = 0; p < 4; p++) unpack2(acc[p][j], h[2 * p], h[2 * p + 1]);
#pragma unroll
        for (int i = 0; i < 8; i++) h[i] = fmaxf(h[i] + b1v[j], 0.0f);
        float* dst = Hs + k * 128 + ((tm ^ (k & 15)) << 3);
        *(float4*)dst = make_float4(h[0], h[1], h[2], h[3]);
        *(float4*)(dst + 4) = make_float4(h[4], h[5], h[6], h[7]);
    }
#pragma unroll
    for (int p = 0; p < 4; p++)
#pragma unroll
        for (int j = 0; j < 8; j++) acc[p][j] = 0ull;

    // ---- phase 2: out = H@W2 + b2 (optionally * rowscale) ----
    bv = ((const float4*)W2)[tid];
    ((float4*)Bs)[tid] = bv;
    __syncthreads();   // covers Hs writes + Bs chunk 0
#pragma unroll 1
    for (int c = 0; c < 16; c++) {
        int cur = c & 1;
        if (c < 15) bv = ((const float4*)(W2 + (size_t)(c + 1) * 1024))[tid];
        mm8_swz(Hs, c * 8, Bs + cur * 1024, acc, tm, rn);
        if (c < 15) ((float4*)(Bs + (cur ^ 1) * 1024))[tid] = bv;
        __syncthreads();
    }
    float b2v[8];
    *(float4*)&b2v[0] = *(const float4*)(b2 + rn);
    *(float4*)&b2v[4] = *(const float4*)(b2 + rn + 4);
    float scv[8];
    if (inv) {
        *(float4*)&scv[0] = *(const float4*)(inv + rowbase + rm);
        *(float4*)&scv[4] = *(const float4*)(inv + rowbase + rm + 4);
    } else {
#pragma unroll
        for (int i = 0; i < 8; i++) scv[i] = 1.0f;
    }
#pragma unroll
    for (int p = 0; p < 4; p++) {
        float v0[8], v1[8];
#pragma unroll
        for (int j = 0; j < 8; j++) {
            unpack2(acc[p][j], v0[j], v1[j]);
            v0[j] = (v0[j] + b2v[j]) * scv[2 * p];
            v1[j] = (v1[j] + b2v[j]) * scv[2 * p + 1];
        }
        float* o0 = out + (rowbase + rm + 2 * p) * D + rn;
        float* o1 = o0 + D;
        *(float4*)o0 = make_float4(v0[0], v0[1], v0[2], v0[3]);
        *(float4*)(o0 + 4) = make_float4(v0[4], v0[5], v0[6], v0[7]);
        *(float4*)o1 = make_float4(v1[0], v1[1], v1[2], v1[3]);
        *(float4*)(o1 + 4) = make_float4(v1[4], v1[5], v1[6], v1[7]);
    }
}

// ---------------- update GEMM: out = [S0|S1|S2] @ W + bias (in-place safe per-CTA) ----
__global__ __launch_bounds__(256, 2) void k_update(
    const float* __restrict__ S0, const float* __restrict__ S1, const float* __restrict__ S2,
    const float* __restrict__ W, const float* __restrict__ bias,
    float* __restrict__ out, int nsrc) {
    __shared__ float As[2][1024];
    __shared__ float Bs[2][1024];
    const int tid = threadIdx.x;
    const int tm = tid >> 4, tn = tid & 15;
    const int rm = tm << 3, rn = tn << 3;
    const size_t rowbase = (size_t)blockIdx.x * 128;
    const int lm = tid >> 1;
    const int lq = (tid & 1) << 2;
    const int nch = nsrc * 16;

    ull acc[4][8];
#pragma unroll
    for (int p = 0; p < 4; p++)
#pragma unroll
        for (int j = 0; j < 8; j++) acc[p][j] = 0ull;

    const float* S;
    S = S0;
    float4 av = *(const float4*)(S + (rowbase + lm) * D + lq);
    float4 bv = ((const float4*)W)[tid];
    {
        float* a0 = &As[0][lq * 128 + lm];
        a0[0] = av.x; a0[128] = av.y; a0[256] = av.z; a0[384] = av.w;
        ((float4*)Bs[0])[tid] = bv;
    }
    __syncthreads();
#pragma unroll 1
    for (int c = 0; c < nch; c++) {
        int cur = c & 1;
        if (c + 1 < nch) {
            int s = (c + 1) >> 4;
            S = (s == 0) ? S0 : ((s == 1) ? S1 : S2);
            av = *(const float4*)(S + (rowbase + lm) * D + ((c + 1) & 15) * 8 + lq);
            bv = ((const float4*)(W + (size_t)(c + 1) * 1024))[tid];
        }
        mm8(As[cur], Bs[cur], acc, rm, rn);
        if (c + 1 < nch) {
            float* a0 = &As[cur ^ 1][lq * 128 + lm];
            a0[0] = av.x; a0[128] = av.y; a0[256] = av.z; a0[384] = av.w;
            ((float4*)Bs[cur ^ 1])[tid] = bv;
        }
        __syncthreads();
    }
    float bvv[8];
    *(float4*)&bvv[0] = *(const float4*)(bias + rn);
    *(float4*)&bvv[4] = *(const float4*)(bias + rn + 4);
#pragma unroll
    for (int p = 0; p < 4; p++) {
        float v0[8], v1[8];
#pragma unroll
        for (int j = 0; j < 8; j++) {
            unpack2(acc[p][j], v0[j], v1[j]);
            v0[j] += bvv[j];
            v1[j] += bvv[j];
        }
        float* o0 = out + (rowbase + rm + 2 * p) * D + rn;
        float* o1 = o0 + D;
        *(float4*)o0 = make_float4(v0[0], v0[1], v0[2], v0[3]);
        *(float4*)(o0 + 4) = make_float4(v0[4], v0[5], v0[6], v0[7]);
        *(float4*)o1 = make_float4(v1[0], v1[1], v1[2], v1[3]);
        *(float4*)(o1 + 4) = make_float4(v1[4], v1[5], v1[6], v1[7]);
    }
}

// ---------------- CSR aggregation: one warp per node ----------------
__global__ void k_aggr(const float* __restrict__ msg, const int* __restrict__ adj,
                       const int* __restrict__ off, const int* __restrict__ cnt,
                       const float* __restrict__ inv, float* __restrict__ out, int n) {
    int w = (blockIdx.x * blockDim.x + threadIdx.x) >> 5;
    int lane = threadIdx.x & 31;
    if (w >= n) return;
    int o = off[w], d = cnt[w];
    float4 acc = make_float4(0.f, 0.f, 0.f, 0.f);
    for (int j = 0; j < d; j++) {
        int s = adj[o + j];
        float4 v = *(const float4*)(msg + (size_t)s * D + lane * 4);
        acc.x += v.x; acc.y += v.y; acc.z += v.z; acc.w += v.w;
    }
    float sc = inv[w];
    *(float4*)(out + (size_t)w * D + lane * 4) =
        make_float4(acc.x * sc, acc.y * sc, acc.z * sc, acc.w * sc);
}

// ---------------- host launcher ----------------
extern "C" void kernel_launch(void* const* d_in, const int* in_sizes, int n_in,
                              void* d_out, int out_size) {
    const void* l_ei = d_in[0];
    const void* c_ei = d_in[1];
    const float* l_init  = (const float*)d_in[2];
    const float* c_init  = (const float*)d_in[3];
    const float* w_l2c1 = (const float*)d_in[4],  *b_l2c1 = (const float*)d_in[5];
    const float* w_l2c2 = (const float*)d_in[6],  *b_l2c2 = (const float*)d_in[7];
    const float* w_c2l1 = (const float*)d_in[8],  *b_c2l1 = (const float*)d_in[9];
    const float* w_c2l2 = (const float*)d_in[10], *b_c2l2 = (const float*)d_in[11];
    const float* w_l2l1 = (const float*)d_in[12], *b_l2l1 = (const float*)d_in[13];
    const float* w_l2l2 = (const float*)d_in[14], *b_l2l2 = (const float*)d_in[15];
    const float* w_cu   = (const float*)d_in[16], *b_cu   = (const float*)d_in[17];
    const float* w_lu   = (const float*)d_in[18], *b_lu   = (const float*)d_in[19];
    (void)in_sizes; (void)n_in; (void)out_size;

    float *l_emb, *c_emb, *msg_l, *msg_c, *l2l, *aggr_l, *aggr_c, *inv_l, *inv_c;
    int *cnt_l, *cnt_c, *off_l, *off_c, *cur_l, *cur_c, *adj_l, *adj_c;
    cudaGetSymbolAddress((void**)&l_emb,  g_l_emb);
    cudaGetSymbolAddress((void**)&c_emb,  g_c_emb);
    cudaGetSymbolAddress((void**)&msg_l,  g_msg_l);
    cudaGetSymbolAddress((void**)&msg_c,  g_msg_c);
    cudaGetSymbolAddress((void**)&l2l,    g_l2l);
    cudaGetSymbolAddress((void**)&aggr_l, g_aggr_l);
    cudaGetSymbolAddress((void**)&aggr_c, g_aggr_c);
    cudaGetSymbolAddress((void**)&inv_l,  g_inv_l);
    cudaGetSymbolAddress((void**)&inv_c,  g_inv_c);
    cudaGetSymbolAddress((void**)&cnt_l,  g_cnt_l);
    cudaGetSymbolAddress((void**)&cnt_c,  g_cnt_c);
    cudaGetSymbolAddress((void**)&off_l,  g_off_l);
    cudaGetSymbolAddress((void**)&off_c,  g_off_c);
    cudaGetSymbolAddress((void**)&cur_l,  g_cur_l);
    cudaGetSymbolAddress((void**)&cur_c,  g_cur_c);
    cudaGetSymbolAddress((void**)&adj_l,  g_adj_l);
    cudaGetSymbolAddress((void**)&adj_c,  g_adj_c);

    const int MLP_SMEM = (2048 + 2048 + 16384) * 4;   // 81920 B dynamic
    cudaFuncSetAttribute(k_mlp2, cudaFuncAttributeMaxDynamicSharedMemorySize, MLP_SMEM);

    // ---- graph construction (recomputed every replay; deterministic up to fp order) ----
    cudaMemsetAsync(cnt_l, 0, L_SIZE * sizeof(int));
    cudaMemsetAsync(cnt_c, 0, C_SIZE * sizeof(int));
    k_detect<<<1, 256>>>((const unsigned*)l_ei);
    k_hist<<<E_SIZE / 256, 256>>>(l_ei, c_ei);

    k_bsum<<<L_SIZE / 1024, 256>>>(cnt_l);
    k_scan_base<<<1, 1>>>(L_SIZE / 1024);
    k_scan_write<<<L_SIZE / 1024, 256>>>(cnt_l, off_l, cur_l);

    k_bsum<<<C_SIZE / 1024, 256>>>(cnt_c);
    k_scan_base<<<1, 1>>>(C_SIZE / 1024);
    k_scan_write<<<C_SIZE / 1024, 256>>>(cnt_c, off_c, cur_c);

    k_fill<<<E_SIZE / 256, 256>>>(l_ei, c_ei);
    k_inv<<<L_SIZE / 256, 256>>>();

    // ---- init embeddings ----
    k_init<<<(L_SIZE * D / 4) / 256, 256>>>((float4*)l_emb, (const float4*)l_init, L_SIZE * D / 4);
    k_init<<<(C_SIZE * D / 4) / 256, 256>>>((float4*)c_emb, (const float4*)c_init, C_SIZE * D / 4);

    // ---- message-passing iterations ----
    for (int it = 0; it < N_ITERS; it++) {
        k_mlp2<<<L_SIZE / 128, 256, MLP_SMEM>>>(l_emb, w_l2c1, b_l2c1, w_l2c2, b_l2c2,
                                                inv_l, msg_l, 0);
        k_mlp2<<<C_SIZE / 128, 256, MLP_SMEM>>>(c_emb, w_c2l1, b_c2l1, w_c2l2, b_c2l2,
                                                inv_c, msg_c, 0);
        k_mlp2<<<L_SIZE / 128, 256, MLP_SMEM>>>(l_emb, w_l2l1, b_l2l1, w_l2l2, b_l2l2,
                                                nullptr, l2l, 1);

        k_aggr<<<C_SIZE / 8, 256>>>(msg_l, adj_c, off_c, cnt_c, inv_c, aggr_c, C_SIZE);
        k_update<<<C_SIZE / 128, 256>>>(c_emb, aggr_c, nullptr, w_cu, b_cu, c_emb, 2);

        k_aggr<<<L_SIZE / 8, 256>>>(msg_c, adj_l, off_l, cnt_l, inv_l, aggr_l, L_SIZE);
        float* lout = (it == N_ITERS - 1) ? (float*)d_out : l_emb;
        k_update<<<L_SIZE / 128, 256>>>(l_emb, aggr_l, l2l, w_lu, b_lu, lout, 3);
    }
}

// round 4
// speedup vs baseline: 1.2386x; 1.2386x over previous
#include <cuda_runtime.h>
#include <cuda_bf16.h>
#include <cstdint>

#define L_SIZE 65536
#define C_SIZE 32768
#define E_SIZE 262144
#define D 128
#define N_ITERS 4

using bf16 = __nv_bfloat16;

// ================= device scratch =================
__device__ __align__(16) bf16 g_lemb_h[(size_t)L_SIZE * D];
__device__ __align__(16) bf16 g_lemb_l[(size_t)L_SIZE * D];
__device__ __align__(16) bf16 g_cemb_h[(size_t)C_SIZE * D];
__device__ __align__(16) bf16 g_cemb_l[(size_t)C_SIZE * D];
__device__ __align__(16) float g_msg_l[(size_t)L_SIZE * D];
__device__ __align__(16) float g_msg_c[(size_t)C_SIZE * D];
__device__ __align__(16) bf16 g_l2l_h[(size_t)L_SIZE * D];
__device__ __align__(16) bf16 g_l2l_l[(size_t)L_SIZE * D];
__device__ __align__(16) bf16 g_agl_h[(size_t)L_SIZE * D];
__device__ __align__(16) bf16 g_agl_l[(size_t)L_SIZE * D];
__device__ __align__(16) bf16 g_agc_h[(size_t)C_SIZE * D];
__device__ __align__(16) bf16 g_agc_l[(size_t)C_SIZE * D];
__device__ __align__(16) bf16 g_wimg_h[22 * 8192];
__device__ __align__(16) bf16 g_wimg_l[22 * 8192];
__device__ int   g_cnt_l[L_SIZE], g_cnt_c[C_SIZE];
__device__ int   g_off_l[L_SIZE], g_off_c[C_SIZE];
__device__ int   g_cur_l[L_SIZE], g_cur_c[C_SIZE];
__device__ int   g_adj_c[E_SIZE];
__device__ int   g_adj_l[E_SIZE];
__device__ float g_inv_l[L_SIZE], g_inv_c[C_SIZE];
__device__ int   g_bsum[64];
__device__ int   g_idx64;

// ================= helpers =================
__device__ __forceinline__ uint32_t smem_u32(const void* p) {
    uint32_t a;
    asm("{ .reg .u64 t; cvta.to.shared.u64 t, %1; cvt.u32.u64 %0, t; }" : "=r"(a) : "l"(p));
    return a;
}
__device__ __forceinline__ int swz(int off) { return off ^ ((off >> 3) & 0x70); }

__device__ __forceinline__ void split_bf(float v, unsigned short& h, unsigned short& l) {
    bf16 hb = __float2bfloat16_rn(v);
    bf16 lb = __float2bfloat16_rn(v - __bfloat162float(hb));
    h = __bfloat16_as_ushort(hb);
    l = __bfloat16_as_ushort(lb);
}

__device__ __forceinline__ void ldmx4(uint32_t* r, uint32_t addr) {
    asm volatile("ldmatrix.sync.aligned.m8n8.x4.shared.b16 {%0,%1,%2,%3}, [%4];"
                 : "=r"(r[0]), "=r"(r[1]), "=r"(r[2]), "=r"(r[3]) : "r"(addr));
}

__device__ __forceinline__ void mma16816(float (&c)[4], const uint32_t* a, const uint32_t* b) {
    asm volatile(
        "mma.sync.aligned.m16n8k16.row.col.f32.bf16.bf16.f32 "
        "{%0,%1,%2,%3}, {%4,%5,%6,%7}, {%8,%9}, {%0,%1,%2,%3};"
        : "+f"(c[0]), "+f"(c[1]), "+f"(c[2]), "+f"(c[3])
        : "r"(a[0]), "r"(a[1]), "r"(a[2]), "r"(a[3]), "r"(b[0]), "r"(b[1]));
}

// SMEM map (bytes): 64 b1s[128], 576 b2s[128],
// 2048: A tiles [Ah0,Ah1,Al0,Al1] 4x16KB; 67584: W tiles [Wh0,Wh1,Wl0,Wl1] 4x16KB.
// fp32 stage (128x132) overlays A region (+2KB of W region) after last MMA.
#define SMEM_TC (2048 + 8 * 16384)
#define A_OFF 2048
#define W_OFF (2048 + 4 * 16384)

// ================= edge-index dtype handling =================
__device__ __forceinline__ int eidx(const void* p, int i, int f) {
    if (f) return (int)((const unsigned long long*)p)[i];
    return ((const int*)p)[i];
}
__global__ void k_detect(const unsigned* p) {
    unsigned v = p[2 * threadIdx.x + 1];
    __shared__ int anynz;
    if (threadIdx.x == 0) anynz = 0;
    __syncthreads();
    unsigned b = __ballot_sync(0xffffffffu, v != 0u);
    if ((threadIdx.x & 31) == 0 && b) atomicExch(&anynz, 1);
    __syncthreads();
    if (threadIdx.x == 0) g_idx64 = (anynz == 0) ? 1 : 0;
}
__global__ void k_hist(const void* lp, const void* cp) {
    int e = blockIdx.x * blockDim.x + threadIdx.x;
    int f = g_idx64;
    atomicAdd(&g_cnt_l[eidx(lp, e, f)], 1);
    atomicAdd(&g_cnt_c[eidx(cp, e, f)], 1);
}
__global__ void k_bsum(const int* __restrict__ cnt) {
    __shared__ int sh[256];
    int base = blockIdx.x * 1024 + threadIdx.x;
    int s = 0;
#pragma unroll
    for (int t = 0; t < 4; t++) s += cnt[base + t * 256];
    sh[threadIdx.x] = s;
    __syncthreads();
    for (int o = 128; o > 0; o >>= 1) {
        if (threadIdx.x < o) sh[threadIdx.x] += sh[threadIdx.x + o];
        __syncthreads();
    }
    if (threadIdx.x == 0) g_bsum[blockIdx.x] = sh[0];
}
__global__ void k_scan_base(int G) {
    int run = 0;
    for (int i = 0; i < G; i++) { int v = g_bsum[i]; g_bsum[i] = run; run += v; }
}
__global__ void k_scan_write(const int* __restrict__ cnt, int* __restrict__ off,
                             int* __restrict__ cur) {
    __shared__ int sh[256];
    int tid = threadIdx.x;
    int base4 = blockIdx.x * 1024 + tid * 4;
    int4 v = *(const int4*)(cnt + base4);
    int tsum = v.x + v.y + v.z + v.w;
    sh[tid] = tsum;
    __syncthreads();
    for (int o = 1; o < 256; o <<= 1) {
        int t = (tid >= o) ? sh[tid - o] : 0;
        __syncthreads();
        sh[tid] += t;
        __syncthreads();
    }
    int e = g_bsum[blockIdx.x] + sh[tid] - tsum;
    off[base4 + 0] = e; cur[base4 + 0] = e; e += v.x;
    off[base4 + 1] = e; cur[base4 + 1] = e; e += v.y;
    off[base4 + 2] = e; cur[base4 + 2] = e; e += v.z;
    off[base4 + 3] = e; cur[base4 + 3] = e;
}
__global__ void k_fill(const void* lp, const void* cp) {
    int e = blockIdx.x * blockDim.x + threadIdx.x;
    int f = g_idx64;
    int li = eidx(lp, e, f);
    int ci = eidx(cp, e, f);
    g_adj_c[atomicAdd(&g_cur_c[ci], 1)] = li;
    g_adj_l[atomicAdd(&g_cur_l[li], 1)] = ci;
}
__global__ void k_inv() {
    int i = blockIdx.x * blockDim.x + threadIdx.x;
    if (i < L_SIZE) { int c = g_cnt_l[i]; g_inv_l[i] = c ? rsqrtf((float)c) : 0.0f; }
    if (i < C_SIZE) { int c = g_cnt_c[i]; g_inv_c[i] = c ? rsqrtf((float)c) : 0.0f; }
}

// ================= init / weight prep =================
__global__ void k_init2(bf16* __restrict__ dh, bf16* __restrict__ dl,
                        const float* __restrict__ init, int nthreads) {
    int i = blockIdx.x * blockDim.x + threadIdx.x;
    if (i >= nthreads) return;
    int c8 = (i & 15) * 8;
    size_t base = (size_t)(i >> 4) * 128 + c8;
    unsigned short hh[8], ll[8];
#pragma unroll
    for (int j = 0; j < 8; j++) split_bf(init[c8 + j], hh[j], ll[j]);
    uint4 H, L;
    H.x = hh[0] | ((uint32_t)hh[1] << 16); H.y = hh[2] | ((uint32_t)hh[3] << 16);
    H.z = hh[4] | ((uint32_t)hh[5] << 16); H.w = hh[6] | ((uint32_t)hh[7] << 16);
    L.x = ll[0] | ((uint32_t)ll[1] << 16); L.y = ll[2] | ((uint32_t)ll[3] << 16);
    L.z = ll[4] | ((uint32_t)ll[5] << 16); L.w = ll[6] | ((uint32_t)ll[7] << 16);
    *(uint4*)(dh + base) = H;
    *(uint4*)(dl + base) = L;
}

// half h holds Bt[n][k] = W[k0+k][n], n in [0,128), k in [0,64), SW128-swizzled image.
__global__ void k_wprep(const float* w0, const float* w1, const float* w2, const float* w3,
                        const float* w4, const float* w5, const float* wcu, const float* wlu) {
    int half = blockIdx.x;
    const float* W;
    int k0;
    if (half < 12) {
        const float* ws[6] = {w0, w1, w2, w3, w4, w5};
        W = ws[half >> 1];
        k0 = (half & 1) * 64;
    } else if (half < 16) {
        W = wcu; k0 = (half - 12) * 64;
    } else {
        W = wlu; k0 = (half - 16) * 64;
    }
    bf16* oh = g_wimg_h + (size_t)half * 8192;
    bf16* ol = g_wimg_l + (size_t)half * 8192;
    for (int idx = threadIdx.x; idx < 8192; idx += blockDim.x) {
        int n = idx >> 6, k = idx & 63;
        float v = W[(size_t)(k0 + k) * 128 + n];
        unsigned short h, l;
        split_bf(v, h, l);
        int sw = swz(n * 128 + k * 2);
        *(unsigned short*)((char*)oh + sw) = h;
        *(unsigned short*)((char*)ol + sw) = l;
    }
}

// ================= smem tile fills =================
__device__ __forceinline__ void load_A(char* sm, const bf16* __restrict__ Xh,
                                       const bf16* __restrict__ Xl, size_t rowbase,
                                       int swap, int tid) {
    int r = tid >> 1, h = tid & 1;
    int sr = swap ? (r ^ 1) : r;
    const uint4* shp = (const uint4*)(Xh + (rowbase + sr) * 128 + h * 64);
    const uint4* slp = (const uint4*)(Xl + (rowbase + sr) * 128 + h * 64);
    char* dh = sm + A_OFF + h * 16384;
    char* dl = sm + A_OFF + 2 * 16384 + h * 16384;
#pragma unroll
    for (int u = 0; u < 8; u++) {
        int sw = swz(r * 128 + u * 16);
        *(uint4*)(dh + sw) = shp[u];
        *(uint4*)(dl + sw) = slp[u];
    }
}

__device__ __forceinline__ void load_W(char* sm, int whalf, int tid, int stride) {
    const uint4* sh = (const uint4*)(g_wimg_h + (size_t)whalf * 8192);
    const uint4* sl = (const uint4*)(g_wimg_l + (size_t)whalf * 8192);
    uint4* d = (uint4*)(sm + W_OFF);
    for (int i = tid; i < 2048; i += stride) d[i] = sh[i];
    for (int i = tid; i < 2048; i += stride) d[2048 + i] = sl[i];
}

// ================= warp GEMM over K=128 (3-term hi/lo split) =================
__device__ __forceinline__ void warp_mma_k128(float (&acc)[16][4], uint32_t a_base,
                                              uint32_t w_base, int lane, int wrow0) {
#pragma unroll 1
    for (int kc = 0; kc < 8; kc++) {
        int half = kc >> 2;
        int kb = (kc & 3) * 32;                 // byte offset of 16-k group within half-row
        uint32_t ah[4], al[4];
        int arow = wrow0 + (lane & 15);
        int acol = kb + ((lane >> 4) << 4);
        uint32_t aaddr = a_base + half * 16384 + swz(arow * 128 + acol);
        ldmx4(ah, aaddr);
        ldmx4(al, aaddr + 32768);
        int brow = (lane & 7) + ((lane >> 4) & 1) * 8;
        int bcol = kb + (((lane >> 3) & 1) << 4);
#pragma unroll
        for (int nh = 0; nh < 2; nh++) {
            uint32_t bh[16], bl[16];
#pragma unroll
            for (int gg = 0; gg < 4; gg++) {
                int n0 = nh * 64 + gg * 16;
                uint32_t baddr = w_base + half * 16384 + swz((n0 + brow) * 128 + bcol);
                ldmx4(&bh[gg * 4], baddr);
                ldmx4(&bl[gg * 4], baddr + 32768);
            }
#pragma unroll
            for (int term = 0; term < 3; term++) {
                const uint32_t* A = (term == 2) ? al : ah;
                const uint32_t* B = (term == 1) ? bl : bh;
#pragma unroll
                for (int t = 0; t < 8; t++)
                    mma16816(acc[nh * 8 + t], A, &B[(t >> 1) * 4 + (t & 1) * 2]);
            }
        }
    }
}

// fragment -> relu/bias -> split -> swizzled A tiles (H for phase 2)
__device__ __forceinline__ void store_H(char* sm, float (&acc)[16][4],
                                        const float* __restrict__ b1s, int lane, int wrow0) {
    int g = (lane >> 2) & 7, tig = lane & 3;
    int row0 = wrow0 + g, row1 = row0 + 8;
#pragma unroll
    for (int t = 0; t < 16; t++) {
        int n = t * 8 + 2 * tig;
        float bz0 = b1s[n], bz1 = b1s[n + 1];
        float v00 = fmaxf(acc[t][0] + bz0, 0.0f);
        float v01 = fmaxf(acc[t][1] + bz1, 0.0f);
        float v10 = fmaxf(acc[t][2] + bz0, 0.0f);
        float v11 = fmaxf(acc[t][3] + bz1, 0.0f);
        unsigned short h00, l00, h01, l01, h10, l10, h11, l11;
        split_bf(v00, h00, l00); split_bf(v01, h01, l01);
        split_bf(v10, h10, l10); split_bf(v11, h11, l11);
        int half = n >> 6, kk = n & 63;
        char* dh = sm + A_OFF + half * 16384;
        char* dl = dh + 32768;
        int sw0 = swz(row0 * 128 + kk * 2);
        int sw1 = swz(row1 * 128 + kk * 2);
        *(uint32_t*)(dh + sw0) = h00 | ((uint32_t)h01 << 16);
        *(uint32_t*)(dl + sw0) = l00 | ((uint32_t)l01 << 16);
        *(uint32_t*)(dh + sw1) = h10 | ((uint32_t)h11 << 16);
        *(uint32_t*)(dl + sw1) = l10 | ((uint32_t)l11 << 16);
    }
}

// fragment -> bias -> fp32 stage
__device__ __forceinline__ void acc_to_stage(float* __restrict__ stage, float (&acc)[16][4],
                                             const float* __restrict__ bs, int lane, int wrow0) {
    int g = (lane >> 2) & 7, tig = lane & 3;
    int row0 = wrow0 + g, row1 = row0 + 8;
#pragma unroll
    for (int t = 0; t < 16; t++) {
        int n = t * 8 + 2 * tig;
        float bz0 = bs[n], bz1 = bs[n + 1];
        *(float2*)(stage + row0 * 132 + n) = make_float2(acc[t][0] + bz0, acc[t][1] + bz1);
        *(float2*)(stage + row1 * 132 + n) = make_float2(acc[t][2] + bz0, acc[t][3] + bz1);
    }
}

// ================= staged epilogue: smem fp32 -> gmem =================
__device__ __forceinline__ void epilogue_writer(
    const float* __restrict__ stage, size_t rowbase,
    const float* __restrict__ inv, float* __restrict__ outf,
    bf16* __restrict__ outh, bf16* __restrict__ outl, int tid) {
    int r = tid >> 1, h = tid & 1;
    size_t grow = rowbase + r;
    const float4* sr4 = (const float4*)(stage + r * 132 + h * 64);
    if (outf) {
        float sc = inv ? inv[grow] : 1.0f;
        float4* of = (float4*)(outf + grow * 128 + h * 64);
#pragma unroll
        for (int u = 0; u < 16; u++) {
            float4 v = sr4[u];
            v.x *= sc; v.y *= sc; v.z *= sc; v.w *= sc;
            of[u] = v;
        }
    }
    if (outh) {
        uint4* oh = (uint4*)(outh + grow * 128 + h * 64);
        uint4* ol = (uint4*)(outl + grow * 128 + h * 64);
#pragma unroll
        for (int u = 0; u < 8; u++) {
            float4 a = sr4[2 * u], b = sr4[2 * u + 1];
            unsigned short hh[8], ll[8];
            split_bf(a.x, hh[0], ll[0]); split_bf(a.y, hh[1], ll[1]);
            split_bf(a.z, hh[2], ll[2]); split_bf(a.w, hh[3], ll[3]);
            split_bf(b.x, hh[4], ll[4]); split_bf(b.y, hh[5], ll[5]);
            split_bf(b.z, hh[6], ll[6]); split_bf(b.w, hh[7], ll[7]);
            uint4 H, L;
            H.x = hh[0] | ((uint32_t)hh[1] << 16); H.y = hh[2] | ((uint32_t)hh[3] << 16);
            H.z = hh[4] | ((uint32_t)hh[5] << 16); H.w = hh[6] | ((uint32_t)hh[7] << 16);
            L.x = ll[0] | ((uint32_t)ll[1] << 16); L.y = ll[2] | ((uint32_t)ll[3] << 16);
            L.z = ll[4] | ((uint32_t)ll[5] << 16); L.w = ll[6] | ((uint32_t)ll[7] << 16);
            oh[u] = H;
            ol[u] = L;
        }
    }
}

// ================= fused 2-layer MLP (HMMA) =================
__global__ __launch_bounds__(256, 1) void k_mlp_tc(
    const bf16* __restrict__ Xh, const bf16* __restrict__ Xl,
    int w1half, int w2half,
    const float* __restrict__ b1, const float* __restrict__ b2,
    const float* __restrict__ inv, float* __restrict__ outf,
    bf16* __restrict__ outh, bf16* __restrict__ outl, int swap) {
    extern __shared__ __align__(1024) char sm[];
    uint32_t smem_base = smem_u32(sm);
    float* b1s = (float*)(sm + 64);
    float* b2s = (float*)(sm + 576);
    float* stage = (float*)(sm + A_OFF);
    int tid = threadIdx.x, wid = tid >> 5, lane = tid & 31;
    int wrow0 = wid * 16;
    size_t rowbase = (size_t)blockIdx.x * 128;

    if (tid < 128) b1s[tid] = b1[tid];
    else b2s[tid - 128] = b2[tid - 128];
    load_A(sm, Xh, Xl, rowbase, swap, tid);
    load_W(sm, w1half, tid, 256);
    __syncthreads();

    float acc[16][4];
#pragma unroll
    for (int t = 0; t < 16; t++)
#pragma unroll
        for (int j = 0; j < 4; j++) acc[t][j] = 0.0f;

    // phase 1: H = relu(X@W1 + b1)
    warp_mma_k128(acc, smem_base + A_OFF, smem_base + W_OFF, lane, wrow0);
    __syncthreads();

    store_H(sm, acc, b1s, lane, wrow0);
    load_W(sm, w2half, tid, 256);
#pragma unroll
    for (int t = 0; t < 16; t++)
#pragma unroll
        for (int j = 0; j < 4; j++) acc[t][j] = 0.0f;
    __syncthreads();

    // phase 2: out = H@W2 + b2
    warp_mma_k128(acc, smem_base + A_OFF, smem_base + W_OFF, lane, wrow0);
    __syncthreads();

    acc_to_stage(stage, acc, b2s, lane, wrow0);
    __syncthreads();
    epilogue_writer(stage, rowbase, inv, outf, outh, outl, tid);
}

// ================= update GEMM (HMMA, K chunked by 128) =================
__global__ __launch_bounds__(256, 1) void k_upd_tc(
    const bf16* __restrict__ S0h, const bf16* __restrict__ S0l,
    const bf16* __restrict__ S1h, const bf16* __restrict__ S1l,
    const bf16* __restrict__ S2h, const bf16* __restrict__ S2l,
    int whalf, const float* __restrict__ bias,
    bf16* __restrict__ outh, bf16* __restrict__ outl,
    float* __restrict__ outf, int nchunk) {
    extern __shared__ __align__(1024) char sm[];
    uint32_t smem_base = smem_u32(sm);
    float* bs = (float*)(sm + 64);
    float* stage = (float*)(sm + A_OFF);
    int tid = threadIdx.x, wid = tid >> 5, lane = tid & 31;
    int wrow0 = wid * 16;
    size_t rowbase = (size_t)blockIdx.x * 128;

    if (tid < 128) bs[tid] = bias[tid];

    float acc[16][4];
#pragma unroll
    for (int t = 0; t < 16; t++)
#pragma unroll
        for (int j = 0; j < 4; j++) acc[t][j] = 0.0f;

#pragma unroll 1
    for (int c = 0; c < nchunk; c++) {
        if (c) __syncthreads();
        const bf16* Sh = (c == 0) ? S0h : (c == 1) ? S1h : S2h;
        const bf16* Sl = (c == 0) ? S0l : (c == 1) ? S1l : S2l;
        load_A(sm, Sh, Sl, rowbase, 0, tid);
        load_W(sm, whalf + 2 * c, tid, 256);
        __syncthreads();
        warp_mma_k128(acc, smem_base + A_OFF, smem_base + W_OFF, lane, wrow0);
    }
    __syncthreads();

    acc_to_stage(stage, acc, bs, lane, wrow0);
    __syncthreads();
    epilogue_writer(stage, rowbase, nullptr, outf, outh, outl, tid);
}

// ================= CSR aggregation -> hi/lo bf16 =================
__global__ void k_aggr(const float* __restrict__ msg, const int* __restrict__ adj,
                       const int* __restrict__ off, const int* __restrict__ cnt,
                       const float* __restrict__ inv,
                       bf16* __restrict__ outh, bf16* __restrict__ outl, int n) {
    int w = (blockIdx.x * blockDim.x + threadIdx.x) >> 5;
    int lane = threadIdx.x & 31;
    if (w >= n) return;
    int o = off[w], d = cnt[w];
    float4 acc = make_float4(0.f, 0.f, 0.f, 0.f);
    for (int j = 0; j < d; j++) {
        int s = adj[o + j];
        float4 v = *(const float4*)(msg + (size_t)s * D + lane * 4);
        acc.x += v.x; acc.y += v.y; acc.z += v.z; acc.w += v.w;
    }
    float sc = inv[w];
    acc.x *= sc; acc.y *= sc; acc.z *= sc; acc.w *= sc;
    unsigned short hh[4], ll[4];
    split_bf(acc.x, hh[0], ll[0]); split_bf(acc.y, hh[1], ll[1]);
    split_bf(acc.z, hh[2], ll[2]); split_bf(acc.w, hh[3], ll[3]);
    uint2 H, L;
    H.x = hh[0] | ((uint32_t)hh[1] << 16); H.y = hh[2] | ((uint32_t)hh[3] << 16);
    L.x = ll[0] | ((uint32_t)ll[1] << 16); L.y = ll[2] | ((uint32_t)ll[3] << 16);
    *(uint2*)(outh + (size_t)w * D + lane * 4) = H;
    *(uint2*)(outl + (size_t)w * D + lane * 4) = L;
}

// ================= host launcher =================
extern "C" void kernel_launch(void* const* d_in, const int* in_sizes, int n_in,
                              void* d_out, int out_size) {
    const void* l_ei = d_in[0];
    const void* c_ei = d_in[1];
    const float* l_init = (const float*)d_in[2];
    const float* c_init = (const float*)d_in[3];
    const float* w_l2c1 = (const float*)d_in[4],  *b_l2c1 = (const float*)d_in[5];
    const float* w_l2c2 = (const float*)d_in[6],  *b_l2c2 = (const float*)d_in[7];
    const float* w_c2l1 = (const float*)d_in[8],  *b_c2l1 = (const float*)d_in[9];
    const float* w_c2l2 = (const float*)d_in[10], *b_c2l2 = (const float*)d_in[11];
    const float* w_l2l1 = (const float*)d_in[12], *b_l2l1 = (const float*)d_in[13];
    const float* w_l2l2 = (const float*)d_in[14], *b_l2l2 = (const float*)d_in[15];
    const float* w_cu   = (const float*)d_in[16], *b_cu   = (const float*)d_in[17];
    const float* w_lu   = (const float*)d_in[18], *b_lu   = (const float*)d_in[19];
    (void)in_sizes; (void)n_in; (void)out_size;

    bf16 *lemb_h, *lemb_l, *cemb_h, *cemb_l, *l2l_h, *l2l_l;
    bf16 *agl_h, *agl_l, *agc_h, *agc_l;
    float *msg_l, *msg_c, *inv_l, *inv_c;
    int *cnt_l, *cnt_c, *off_l, *off_c, *adj_l, *adj_c, *cur_l, *cur_c;
    cudaGetSymbolAddress((void**)&lemb_h, g_lemb_h);
    cudaGetSymbolAddress((void**)&lemb_l, g_lemb_l);
    cudaGetSymbolAddress((void**)&cemb_h, g_cemb_h);
    cudaGetSymbolAddress((void**)&cemb_l, g_cemb_l);
    cudaGetSymbolAddress((void**)&l2l_h, g_l2l_h);
    cudaGetSymbolAddress((void**)&l2l_l, g_l2l_l);
    cudaGetSymbolAddress((void**)&agl_h, g_agl_h);
    cudaGetSymbolAddress((void**)&agl_l, g_agl_l);
    cudaGetSymbolAddress((void**)&agc_h, g_agc_h);
    cudaGetSymbolAddress((void**)&agc_l, g_agc_l);
    cudaGetSymbolAddress((void**)&msg_l, g_msg_l);
    cudaGetSymbolAddress((void**)&msg_c, g_msg_c);
    cudaGetSymbolAddress((void**)&inv_l, g_inv_l);
    cudaGetSymbolAddress((void**)&inv_c, g_inv_c);
    cudaGetSymbolAddress((void**)&cnt_l, g_cnt_l);
    cudaGetSymbolAddress((void**)&cnt_c, g_cnt_c);
    cudaGetSymbolAddress((void**)&off_l, g_off_l);
    cudaGetSymbolAddress((void**)&off_c, g_off_c);
    cudaGetSymbolAddress((void**)&adj_l, g_adj_l);
    cudaGetSymbolAddress((void**)&adj_c, g_adj_c);
    cudaGetSymbolAddress((void**)&cur_l, g_cur_l);
    cudaGetSymbolAddress((void**)&cur_c, g_cur_c);

    cudaFuncSetAttribute(k_mlp_tc, cudaFuncAttributeMaxDynamicSharedMemorySize, SMEM_TC);
    cudaFuncSetAttribute(k_upd_tc, cudaFuncAttributeMaxDynamicSharedMemorySize, SMEM_TC);

    // ---- graph construction ----
    cudaMemsetAsync(cnt_l, 0, L_SIZE * sizeof(int));
    cudaMemsetAsync(cnt_c, 0, C_SIZE * sizeof(int));
    k_detect<<<1, 256>>>((const unsigned*)l_ei);
    k_hist<<<E_SIZE / 256, 256>>>(l_ei, c_ei);
    k_bsum<<<L_SIZE / 1024, 256>>>(cnt_l);
    k_scan_base<<<1, 1>>>(L_SIZE / 1024);
    k_scan_write<<<L_SIZE / 1024, 256>>>(cnt_l, off_l, cur_l);
    k_bsum<<<C_SIZE / 1024, 256>>>(cnt_c);
    k_scan_base<<<1, 1>>>(C_SIZE / 1024);
    k_scan_write<<<C_SIZE / 1024, 256>>>(cnt_c, off_c, cur_c);
    k_fill<<<E_SIZE / 256, 256>>>(l_ei, c_ei);
    k_inv<<<L_SIZE / 256, 256>>>();

    // ---- weight images + embedding init ----
    k_wprep<<<22, 256>>>(w_l2c1, w_l2c2, w_c2l1, w_c2l2, w_l2l1, w_l2l2, w_cu, w_lu);
    k_init2<<<(L_SIZE * 16) / 256, 256>>>(lemb_h, lemb_l, l_init, L_SIZE * 16);
    k_init2<<<(C_SIZE * 16) / 256, 256>>>(cemb_h, cemb_l, c_init, C_SIZE * 16);

    // ---- message-passing iterations ----
    for (int it = 0; it < N_ITERS; it++) {
        k_mlp_tc<<<L_SIZE / 128, 256, SMEM_TC>>>(lemb_h, lemb_l, 0, 2, b_l2c1, b_l2c2,
                                                 inv_l, msg_l, nullptr, nullptr, 0);
        k_mlp_tc<<<C_SIZE / 128, 256, SMEM_TC>>>(cemb_h, cemb_l, 4, 6, b_c2l1, b_c2l2,
                                                 inv_c, msg_c, nullptr, nullptr, 0);
        k_mlp_tc<<<L_SIZE / 128, 256, SMEM_TC>>>(lemb_h, lemb_l, 8, 10, b_l2l1, b_l2l2,
                                                 nullptr, nullptr, l2l_h, l2l_l, 1);

        k_aggr<<<C_SIZE / 8, 256>>>(msg_l, adj_c, off_c, cnt_c, inv_c, agc_h, agc_l, C_SIZE);
        k_upd_tc<<<C_SIZE / 128, 256, SMEM_TC>>>(cemb_h, cemb_l, agc_h, agc_l,
                                                 nullptr, nullptr, 12, b_cu,
                                                 cemb_h, cemb_l, nullptr, 2);

        k_aggr<<<L_SIZE / 8, 256>>>(msg_c, adj_l, off_l, cnt_l, inv_l, agl_h, agl_l, L_SIZE);
        float* fo = (it == N_ITERS - 1) ? (float*)d_out : nullptr;
        k_upd_tc<<<L_SIZE / 128, 256, SMEM_TC>>>(lemb_h, lemb_l, agl_h, agl_l,
                                                 l2l_h, l2l_l, 16, b_lu,
                                                 lemb_h, lemb_l, fo, 3);
    }
}

// round 5
// speedup vs baseline: 1.9589x; 1.5816x over previous
#include <cuda_runtime.h>
#include <cuda_bf16.h>
#include <cstdint>

#define L_SIZE 65536
#define C_SIZE 32768
#define E_SIZE 262144
#define D 128
#define N_ITERS 4

using bf16 = __nv_bfloat16;

// ================= device scratch =================
__device__ __align__(16) bf16 g_lemb_h[(size_t)L_SIZE * D];
__device__ __align__(16) bf16 g_lemb_l[(size_t)L_SIZE * D];
__device__ __align__(16) bf16 g_cemb_h[(size_t)C_SIZE * D];
__device__ __align__(16) bf16 g_cemb_l[(size_t)C_SIZE * D];
__device__ __align__(16) float g_msg_l[(size_t)L_SIZE * D];
__device__ __align__(16) float g_msg_c[(size_t)C_SIZE * D];
__device__ __align__(16) bf16 g_l2l_h[(size_t)L_SIZE * D];
__device__ __align__(16) bf16 g_l2l_l[(size_t)L_SIZE * D];
__device__ __align__(16) bf16 g_agl_h[(size_t)L_SIZE * D];
__device__ __align__(16) bf16 g_agl_l[(size_t)L_SIZE * D];
__device__ __align__(16) bf16 g_agc_h[(size_t)C_SIZE * D];
__device__ __align__(16) bf16 g_agc_l[(size_t)C_SIZE * D];
__device__ __align__(16) bf16 g_wimg_h[22 * 8192];
__device__ __align__(16) bf16 g_wimg_l[22 * 8192];
__device__ int   g_cnt_l[L_SIZE], g_cnt_c[C_SIZE];
__device__ int   g_off_l[L_SIZE], g_off_c[C_SIZE];
__device__ int   g_cur_l[L_SIZE], g_cur_c[C_SIZE];
__device__ int   g_adj_c[E_SIZE];
__device__ int   g_adj_l[E_SIZE];
__device__ float g_inv_l[L_SIZE], g_inv_c[C_SIZE];
__device__ int   g_bsum[64];
__device__ int   g_idx64;

// ================= helpers =================
__device__ __forceinline__ uint32_t smem_u32(const void* p) {
    uint32_t a;
    asm("{ .reg .u64 t; cvta.to.shared.u64 t, %1; cvt.u32.u64 %0, t; }" : "=r"(a) : "l"(p));
    return a;
}
__device__ __forceinline__ int swz(int off) { return off ^ ((off >> 3) & 0x70); }

__device__ __forceinline__ void split_bf(float v, unsigned short& h, unsigned short& l) {
    bf16 hb = __float2bfloat16_rn(v);
    bf16 lb = __float2bfloat16_rn(v - __bfloat162float(hb));
    h = __bfloat16_as_ushort(hb);
    l = __bfloat16_as_ushort(lb);
}

__device__ __forceinline__ void ldmx4(uint32_t* r, uint32_t addr) {
    asm volatile("ldmatrix.sync.aligned.m8n8.x4.shared.b16 {%0,%1,%2,%3}, [%4];"
                 : "=r"(r[0]), "=r"(r[1]), "=r"(r[2]), "=r"(r[3]) : "r"(addr));
}

__device__ __forceinline__ void mma16816(float (&c)[4], const uint32_t* a, const uint32_t* b) {
    asm volatile(
        "mma.sync.aligned.m16n8k16.row.col.f32.bf16.bf16.f32 "
        "{%0,%1,%2,%3}, {%4,%5,%6,%7}, {%8,%9}, {%0,%1,%2,%3};"
        : "+f"(c[0]), "+f"(c[1]), "+f"(c[2]), "+f"(c[3])
        : "r"(a[0]), "r"(a[1]), "r"(a[2]), "r"(a[3]), "r"(b[0]), "r"(b[1]));
}

__device__ __forceinline__ void cpa16(uint32_t dst, const void* src) {
    asm volatile("cp.async.cg.shared.global [%0], [%1], 16;" :: "r"(dst), "l"(src) : "memory");
}
#define CP_COMMIT() asm volatile("cp.async.commit_group;" ::: "memory")
#define CP_WAIT(n)  asm volatile("cp.async.wait_group %0;" :: "n"(n) : "memory")

// ===== SMEM maps (bytes) =====
// MLP: 64 b1s[128], 576 b2s[128]; A region @2048 (2 halves x [hi16K|lo16K] = 64K);
//      W1 @ 2048+64K; W2 @ 2048+128K. fp32 stage (128x132) overlays A after phase 2.
#define A_OFF  2048
#define W1_OFF (2048 + 65536)
#define W2_OFF (2048 + 2 * 65536)
#define SMEM_MLP (2048 + 3 * 65536)
// UPD: two 64K slots, each [Ah16K|Al16K|Wh16K|Wl16K]. stage overlays slot 0.
#define SL_OFF 2048
#define SMEM_UPD (2048 + 2 * 65536)

// ================= edge-index dtype handling =================
__device__ __forceinline__ int eidx(const void* p, int i, int f) {
    if (f) return (int)((const unsigned long long*)p)[i];
    return ((const int*)p)[i];
}
__global__ void k_detect(const unsigned* p) {
    unsigned v = p[2 * threadIdx.x + 1];
    __shared__ int anynz;
    if (threadIdx.x == 0) anynz = 0;
    __syncthreads();
    unsigned b = __ballot_sync(0xffffffffu, v != 0u);
    if ((threadIdx.x & 31) == 0 && b) atomicExch(&anynz, 1);
    __syncthreads();
    if (threadIdx.x == 0) g_idx64 = (anynz == 0) ? 1 : 0;
}
__global__ void k_hist(const void* lp, const void* cp) {
    int e = blockIdx.x * blockDim.x + threadIdx.x;
    int f = g_idx64;
    atomicAdd(&g_cnt_l[eidx(lp, e, f)], 1);
    atomicAdd(&g_cnt_c[eidx(cp, e, f)], 1);
}
__global__ void k_bsum(const int* __restrict__ cnt) {
    __shared__ int sh[256];
    int base = blockIdx.x * 1024 + threadIdx.x;
    int s = 0;
#pragma unroll
    for (int t = 0; t < 4; t++) s += cnt[base + t * 256];
    sh[threadIdx.x] = s;
    __syncthreads();
    for (int o = 128; o > 0; o >>= 1) {
        if (threadIdx.x < o) sh[threadIdx.x] += sh[threadIdx.x + o];
        __syncthreads();
    }
    if (threadIdx.x == 0) g_bsum[blockIdx.x] = sh[0];
}
__global__ void k_scan_base(int G) {
    int run = 0;
    for (int i = 0; i < G; i++) { int v = g_bsum[i]; g_bsum[i] = run; run += v; }
}
__global__ void k_scan_write(const int* __restrict__ cnt, int* __restrict__ off,
                             int* __restrict__ cur) {
    __shared__ int sh[256];
    int tid = threadIdx.x;
    int base4 = blockIdx.x * 1024 + tid * 4;
    int4 v = *(const int4*)(cnt + base4);
    int tsum = v.x + v.y + v.z + v.w;
    sh[tid] = tsum;
    __syncthreads();
    for (int o = 1; o < 256; o <<= 1) {
        int t = (tid >= o) ? sh[tid - o] : 0;
        __syncthreads();
        sh[tid] += t;
        __syncthreads();
    }
    int e = g_bsum[blockIdx.x] + sh[tid] - tsum;
    off[base4 + 0] = e; cur[base4 + 0] = e; e += v.x;
    off[base4 + 1] = e; cur[base4 + 1] = e; e += v.y;
    off[base4 + 2] = e; cur[base4 + 2] = e; e += v.z;
    off[base4 + 3] = e; cur[base4 + 3] = e;
}
__global__ void k_fill(const void* lp, const void* cp) {
    int e = blockIdx.x * blockDim.x + threadIdx.x;
    int f = g_idx64;
    int li = eidx(lp, e, f);
    int ci = eidx(cp, e, f);
    g_adj_c[atomicAdd(&g_cur_c[ci], 1)] = li;
    g_adj_l[atomicAdd(&g_cur_l[li], 1)] = ci;
}
__global__ void k_inv() {
    int i = blockIdx.x * blockDim.x + threadIdx.x;
    if (i < L_SIZE) { int c = g_cnt_l[i]; g_inv_l[i] = c ? rsqrtf((float)c) : 0.0f; }
    if (i < C_SIZE) { int c = g_cnt_c[i]; g_inv_c[i] = c ? rsqrtf((float)c) : 0.0f; }
}

// ================= init / weight prep =================
__global__ void k_init2(bf16* __restrict__ dh, bf16* __restrict__ dl,
                        const float* __restrict__ init, int nthreads) {
    int i = blockIdx.x * blockDim.x + threadIdx.x;
    if (i >= nthreads) return;
    int c8 = (i & 15) * 8;
    size_t base = (size_t)(i >> 4) * 128 + c8;
    unsigned short hh[8], ll[8];
#pragma unroll
    for (int j = 0; j < 8; j++) split_bf(init[c8 + j], hh[j], ll[j]);
    uint4 H, L;
    H.x = hh[0] | ((uint32_t)hh[1] << 16); H.y = hh[2] | ((uint32_t)hh[3] << 16);
    H.z = hh[4] | ((uint32_t)hh[5] << 16); H.w = hh[6] | ((uint32_t)hh[7] << 16);
    L.x = ll[0] | ((uint32_t)ll[1] << 16); L.y = ll[2] | ((uint32_t)ll[3] << 16);
    L.z = ll[4] | ((uint32_t)ll[5] << 16); L.w = ll[6] | ((uint32_t)ll[7] << 16);
    *(uint4*)(dh + base) = H;
    *(uint4*)(dl + base) = L;
}

// image `half` holds Bt[n][k] = W[k0+k][n], n in [0,128), k in [0,64), SW128-swizzled.
__global__ void k_wprep(const float* w0, const float* w1, const float* w2, const float* w3,
                        const float* w4, const float* w5, const float* wcu, const float* wlu) {
    int half = blockIdx.x;
    const float* W;
    int k0;
    if (half < 12) {
        const float* ws[6] = {w0, w1, w2, w3, w4, w5};
        W = ws[half >> 1];
        k0 = (half & 1) * 64;
    } else if (half < 16) {
        W = wcu; k0 = (half - 12) * 64;
    } else {
        W = wlu; k0 = (half - 16) * 64;
    }
    bf16* oh = g_wimg_h + (size_t)half * 8192;
    bf16* ol = g_wimg_l + (size_t)half * 8192;
    for (int idx = threadIdx.x; idx < 8192; idx += blockDim.x) {
        int n = idx >> 6, k = idx & 63;
        float v = W[(size_t)(k0 + k) * 128 + n];
        unsigned short h, l;
        split_bf(v, h, l);
        int sw = swz(n * 128 + k * 2);
        *(unsigned short*)((char*)oh + sw) = h;
        *(unsigned short*)((char*)ol + sw) = l;
    }
}

// ================= async tile fills =================
// full-K A tile (2 halves, hi/lo) from row-major hi/lo gmem
__device__ __forceinline__ void issue_A_full(uint32_t a_base, const bf16* __restrict__ Xh,
                                             const bf16* __restrict__ Xl, size_t rowbase,
                                             int swap, int tid) {
    for (int i = tid; i < 2048; i += 256) {
        int row = i >> 4, u = i & 15;
        int half = u >> 3, uu = u & 7;
        int sr = swap ? (row ^ 1) : row;
        size_t goff = (rowbase + sr) * 128 + u * 8;
        uint32_t d = a_base + half * 32768 + swz(row * 128 + uu * 16);
        cpa16(d, Xh + goff);
        cpa16(d + 16384, Xl + goff);
    }
}
// full-K W region (2 image halves, hi/lo) — identity copy of pre-swizzled images
__device__ __forceinline__ void issue_W(uint32_t w_base, int whalf, int tid) {
    for (int i = tid; i < 2048; i += 256) {
        int h = i >> 10, j = i & 1023;
        const uint4* sh = (const uint4*)(g_wimg_h + (size_t)(whalf + h) * 8192) + j;
        const uint4* sl = (const uint4*)(g_wimg_l + (size_t)(whalf + h) * 8192) + j;
        uint32_t d = w_base + h * 32768 + j * 16;
        cpa16(d, sh);
        cpa16(d + 16384, sl);
    }
}
// one K=64 half-slot: A-half hi/lo + W image hi/lo
__device__ __forceinline__ void issue_half(uint32_t slot, const bf16* __restrict__ Sh,
                                           const bf16* __restrict__ Sl, size_t rowbase,
                                           int k64, int wimg, int tid) {
    for (int i = tid; i < 1024; i += 256) {
        int row = i >> 3, uu = i & 7;
        size_t goff = (rowbase + row) * 128 + k64 * 64 + uu * 8;
        uint32_t d = slot + swz(row * 128 + uu * 16);
        cpa16(d, Sh + goff);
        cpa16(d + 16384, Sl + goff);
        cpa16(slot + 32768 + i * 16, (const uint4*)(g_wimg_h + (size_t)wimg * 8192) + i);
        cpa16(slot + 49152 + i * 16, (const uint4*)(g_wimg_l + (size_t)wimg * 8192) + i);
    }
}

// ================= warp GEMM over one K=64 half (3-term hi/lo split) =================
// warp (wid>>1) owns rows [(wid>>1)*32, +32); (wid&1) owns cols [(wid&1)*64, +64)
__device__ __forceinline__ void warp_mma_k64(float (&acc)[16][4], uint32_t a_base,
                                             uint32_t w_base, int lane, int wid) {
    const int wrow0 = (wid >> 1) * 32;
    const int nbase = (wid & 1) * 64;
#pragma unroll
    for (int kc = 0; kc < 4; kc++) {
        int kb = kc * 32;
        uint32_t ah[8], al[8];
#pragma unroll
        for (int mt = 0; mt < 2; mt++) {
            int arow = wrow0 + mt * 16 + (lane & 15);
            int acol = kb + ((lane >> 4) << 4);
            uint32_t aaddr = a_base + swz(arow * 128 + acol);
            ldmx4(ah + mt * 4, aaddr);
            ldmx4(al + mt * 4, aaddr + 16384);
        }
        int brow = (lane & 7) + ((lane >> 4) & 1) * 8;
        int bcol = kb + (((lane >> 3) & 1) << 4);
        uint32_t bh[16], bl[16];
#pragma unroll
        for (int gg = 0; gg < 4; gg++) {
            uint32_t baddr = w_base + swz((nbase + gg * 16 + brow) * 128 + bcol);
            ldmx4(bh + gg * 4, baddr);
            ldmx4(bl + gg * 4, baddr + 16384);
        }
#pragma unroll
        for (int term = 0; term < 3; term++) {
            const uint32_t* A = (term == 2) ? al : ah;
            const uint32_t* B = (term == 1) ? bl : bh;
#pragma unroll
            for (int mt = 0; mt < 2; mt++)
#pragma unroll
                for (int t = 0; t < 8; t++)
                    mma16816(acc[mt * 8 + t], A + mt * 4, B + (t >> 1) * 4 + (t & 1) * 2);
        }
    }
}

// fragment -> relu/bias -> split -> A region (H for phase 2)
__device__ __forceinline__ void store_H(char* sm, float (&acc)[16][4],
                                        const float* __restrict__ b1s, int lane, int wid) {
    const int wrow0 = (wid >> 1) * 32;
    const int nbase = (wid & 1) * 64;
    int g = lane >> 2, tig = lane & 3;
#pragma unroll
    for (int mt = 0; mt < 2; mt++)
#pragma unroll
        for (int nt = 0; nt < 8; nt++) {
            int n = nbase + nt * 8 + 2 * tig;
            int half = n >> 6, kk = n & 63;
            float bz0 = b1s[n], bz1 = b1s[n + 1];
            const float* a = acc[mt * 8 + nt];
            int r0 = wrow0 + mt * 16 + g, r1 = r0 + 8;
            float v00 = fmaxf(a[0] + bz0, 0.0f), v01 = fmaxf(a[1] + bz1, 0.0f);
            float v10 = fmaxf(a[2] + bz0, 0.0f), v11 = fmaxf(a[3] + bz1, 0.0f);
            unsigned short h00, l00, h01, l01, h10, l10, h11, l11;
            split_bf(v00, h00, l00); split_bf(v01, h01, l01);
            split_bf(v10, h10, l10); split_bf(v11, h11, l11);
            char* dh = sm + A_OFF + half * 32768;
            char* dl = dh + 16384;
            int sw0 = swz(r0 * 128 + kk * 2), sw1 = swz(r1 * 128 + kk * 2);
            *(uint32_t*)(dh + sw0) = h00 | ((uint32_t)h01 << 16);
            *(uint32_t*)(dl + sw0) = l00 | ((uint32_t)l01 << 16);
            *(uint32_t*)(dh + sw1) = h10 | ((uint32_t)h11 << 16);
            *(uint32_t*)(dl + sw1) = l10 | ((uint32_t)l11 << 16);
        }
}

// fragment -> bias -> fp32 stage (stride 132)
__device__ __forceinline__ void acc_to_stage(float* __restrict__ stage, float (&acc)[16][4],
                                             const float* __restrict__ bs, int lane, int wid) {
    const int wrow0 = (wid >> 1) * 32;
    const int nbase = (wid & 1) * 64;
    int g = lane >> 2, tig = lane & 3;
#pragma unroll
    for (int mt = 0; mt < 2; mt++)
#pragma unroll
        for (int nt = 0; nt < 8; nt++) {
            int n = nbase + nt * 8 + 2 * tig;
            float bz0 = bs[n], bz1 = bs[n + 1];
            const float* a = acc[mt * 8 + nt];
            int r0 = wrow0 + mt * 16 + g, r1 = r0 + 8;
            *(float2*)(stage + r0 * 132 + n) = make_float2(a[0] + bz0, a[1] + bz1);
            *(float2*)(stage + r1 * 132 + n) = make_float2(a[2] + bz0, a[3] + bz1);
        }
}

// ================= staged epilogue: smem fp32 -> gmem =================
__device__ __forceinline__ void epilogue_writer(
    const float* __restrict__ stage, size_t rowbase,
    const float* __restrict__ inv, float* __restrict__ outf,
    bf16* __restrict__ outh, bf16* __restrict__ outl, int tid) {
    int r = tid >> 1, h = tid & 1;
    size_t grow = rowbase + r;
    const float4* sr4 = (const float4*)(stage + r * 132 + h * 64);
    if (outf) {
        float sc = inv ? inv[grow] : 1.0f;
        float4* of = (float4*)(outf + grow * 128 + h * 64);
#pragma unroll
        for (int u = 0; u < 16; u++) {
            float4 v = sr4[u];
            v.x *= sc; v.y *= sc; v.z *= sc; v.w *= sc;
            of[u] = v;
        }
    }
    if (outh) {
        uint4* oh = (uint4*)(outh + grow * 128 + h * 64);
        uint4* ol = (uint4*)(outl + grow * 128 + h * 64);
#pragma unroll
        for (int u = 0; u < 8; u++) {
            float4 a = sr4[2 * u], b = sr4[2 * u + 1];
            unsigned short hh[8], ll[8];
            split_bf(a.x, hh[0], ll[0]); split_bf(a.y, hh[1], ll[1]);
            split_bf(a.z, hh[2], ll[2]); split_bf(a.w, hh[3], ll[3]);
            split_bf(b.x, hh[4], ll[4]); split_bf(b.y, hh[5], ll[5]);
            split_bf(b.z, hh[6], ll[6]); split_bf(b.w, hh[7], ll[7]);
            uint4 H, L;
            H.x = hh[0] | ((uint32_t)hh[1] << 16); H.y = hh[2] | ((uint32_t)hh[3] << 16);
            H.z = hh[4] | ((uint32_t)hh[5] << 16); H.w = hh[6] | ((uint32_t)hh[7] << 16);
            L.x = ll[0] | ((uint32_t)ll[1] << 16); L.y = ll[2] | ((uint32_t)ll[3] << 16);
            L.z = ll[4] | ((uint32_t)ll[5] << 16); L.w = ll[6] | ((uint32_t)ll[7] << 16);
            oh[u] = H;
            ol[u] = L;
        }
    }
}

// ================= fused 2-layer MLP (HMMA, all weights resident) =================
__global__ __launch_bounds__(256, 1) void k_mlp_tc(
    const bf16* __restrict__ Xh, const bf16* __restrict__ Xl,
    int w1half, int w2half,
    const float* __restrict__ b1, const float* __restrict__ b2,
    const float* __restrict__ inv, float* __restrict__ outf,
    bf16* __restrict__ outh, bf16* __restrict__ outl, int swap) {
    extern __shared__ __align__(1024) char sm[];
    uint32_t smem_base = smem_u32(sm);
    float* b1s = (float*)(sm + 64);
    float* b2s = (float*)(sm + 576);
    float* stage = (float*)(sm + A_OFF);
    int tid = threadIdx.x, wid = tid >> 5, lane = tid & 31;
    size_t rowbase = (size_t)blockIdx.x * 128;

    issue_A_full(smem_base + A_OFF, Xh, Xl, rowbase, swap, tid);
    CP_COMMIT();
    issue_W(smem_base + W1_OFF, w1half, tid);
    CP_COMMIT();
    issue_W(smem_base + W2_OFF, w2half, tid);
    CP_COMMIT();

    if (tid < 128) b1s[tid] = b1[tid];
    else b2s[tid - 128] = b2[tid - 128];

    float acc[16][4];
#pragma unroll
    for (int t = 0; t < 16; t++)
#pragma unroll
        for (int j = 0; j < 4; j++) acc[t][j] = 0.0f;

    CP_WAIT(1);           // A + W1 resident (W2 still streaming)
    __syncthreads();
    warp_mma_k64(acc, smem_base + A_OFF, smem_base + W1_OFF, lane, wid);
    warp_mma_k64(acc, smem_base + A_OFF + 32768, smem_base + W1_OFF + 32768, lane, wid);
    __syncthreads();      // all reads of A done before H overwrites it

    store_H(sm, acc, b1s, lane, wid);
#pragma unroll
    for (int t = 0; t < 16; t++)
#pragma unroll
        for (int j = 0; j < 4; j++) acc[t][j] = 0.0f;
    CP_WAIT(0);           // W2 resident
    __syncthreads();

    warp_mma_k64(acc, smem_base + A_OFF, smem_base + W2_OFF, lane, wid);
    warp_mma_k64(acc, smem_base + A_OFF + 32768, smem_base + W2_OFF + 32768, lane, wid);
    __syncthreads();

    acc_to_stage(stage, acc, b2s, lane, wid);
    __syncthreads();
    epilogue_writer(stage, rowbase, inv, outf, outh, outl, tid);
}

// ================= update GEMM (HMMA, K=64 pipelined, 2 slots) =================
__global__ __launch_bounds__(256, 1) void k_upd_tc(
    const bf16* __restrict__ S0h, const bf16* __restrict__ S0l,
    const bf16* __restrict__ S1h, const bf16* __restrict__ S1l,
    const bf16* __restrict__ S2h, const bf16* __restrict__ S2l,
    int whalf, const float* __restrict__ bias,
    bf16* __restrict__ outh, bf16* __restrict__ outl,
    float* __restrict__ outf, int nchunk) {
    extern __shared__ __align__(1024) char sm[];
    uint32_t smem_base = smem_u32(sm);
    float* bs = (float*)(sm + 64);
    float* stage = (float*)(sm + SL_OFF);
    int tid = threadIdx.x, wid = tid >> 5, lane = tid & 31;
    size_t rowbase = (size_t)blockIdx.x * 128;
    const int H = 2 * nchunk;

    if (tid < 128) bs[tid] = bias[tid];

    issue_half(smem_base + SL_OFF, S0h, S0l, rowbase, 0, whalf, tid);
    CP_COMMIT();
    issue_half(smem_base + SL_OFF + 65536, S0h, S0l, rowbase, 1, whalf + 1, tid);
    CP_COMMIT();

    float acc[16][4];
#pragma unroll
    for (int t = 0; t < 16; t++)
#pragma unroll
        for (int j = 0; j < 4; j++) acc[t][j] = 0.0f;

#pragma unroll 1
    for (int h = 0; h < H; h++) {
        if (h + 1 < H) { CP_WAIT(1); } else { CP_WAIT(0); }
        __syncthreads();
        uint32_t slot = smem_base + SL_OFF + (h & 1) * 65536;
        warp_mma_k64(acc, slot, slot + 32768, lane, wid);
        __syncthreads();
        if (h + 2 < H) {
            int c = (h + 2) >> 1;
            const bf16* Sh = (c == 0) ? S0h : (c == 1) ? S1h : S2h;
            const bf16* Sl = (c == 0) ? S0l : (c == 1) ? S1l : S2l;
            issue_half(smem_base + SL_OFF + (h & 1) * 65536, Sh, Sl, rowbase,
                       (h + 2) & 1, whalf + h + 2, tid);
            CP_COMMIT();
        }
    }

    acc_to_stage(stage, acc, bs, lane, wid);
    __syncthreads();
    epilogue_writer(stage, rowbase, nullptr, outf, outh, outl, tid);
}

// ================= CSR aggregation -> hi/lo bf16 =================
__global__ void k_aggr(const float* __restrict__ msg, const int* __restrict__ adj,
                       const int* __restrict__ off, const int* __restrict__ cnt,
                       const float* __restrict__ inv,
                       bf16* __restrict__ outh, bf16* __restrict__ outl, int n) {
    int w = (blockIdx.x * blockDim.x + threadIdx.x) >> 5;
    int lane = threadIdx.x & 31;
    if (w >= n) return;
    int o = off[w], d = cnt[w];
    float4 acc = make_float4(0.f, 0.f, 0.f, 0.f);
    float4 acc2 = make_float4(0.f, 0.f, 0.f, 0.f);
    int j = 0;
    for (; j + 2 <= d; j += 2) {
        int s0 = adj[o + j], s1 = adj[o + j + 1];
        float4 v0 = *(const float4*)(msg + (size_t)s0 * D + lane * 4);
        float4 v1 = *(const float4*)(msg + (size_t)s1 * D + lane * 4);
        acc.x += v0.x; acc.y += v0.y; acc.z += v0.z; acc.w += v0.w;
        acc2.x += v1.x; acc2.y += v1.y; acc2.z += v1.z; acc2.w += v1.w;
    }
    if (j < d) {
        int s0 = adj[o + j];
        float4 v0 = *(const float4*)(msg + (size_t)s0 * D + lane * 4);
        acc.x += v0.x; acc.y += v0.y; acc.z += v0.z; acc.w += v0.w;
    }
    acc.x += acc2.x; acc.y += acc2.y; acc.z += acc2.z; acc.w += acc2.w;
    float sc = inv[w];
    acc.x *= sc; acc.y *= sc; acc.z *= sc; acc.w *= sc;
    unsigned short hh[4], ll[4];
    split_bf(acc.x, hh[0], ll[0]); split_bf(acc.y, hh[1], ll[1]);
    split_bf(acc.z, hh[2], ll[2]); split_bf(acc.w, hh[3], ll[3]);
    uint2 H, L;
    H.x = hh[0] | ((uint32_t)hh[1] << 16); H.y = hh[2] | ((uint32_t)hh[3] << 16);
    L.x = ll[0] | ((uint32_t)ll[1] << 16); L.y = ll[2] | ((uint32_t)ll[3] << 16);
    *(uint2*)(outh + (size_t)w * D + lane * 4) = H;
    *(uint2*)(outl + (size_t)w * D + lane * 4) = L;
}

// ================= host launcher =================
extern "C" void kernel_launch(void* const* d_in, const int* in_sizes, int n_in,
                              void* d_out, int out_size) {
    const void* l_ei = d_in[0];
    const void* c_ei = d_in[1];
    const float* l_init = (const float*)d_in[2];
    const float* c_init = (const float*)d_in[3];
    const float* w_l2c1 = (const float*)d_in[4],  *b_l2c1 = (const float*)d_in[5];
    const float* w_l2c2 = (const float*)d_in[6],  *b_l2c2 = (const float*)d_in[7];
    const float* w_c2l1 = (const float*)d_in[8],  *b_c2l1 = (const float*)d_in[9];
    const float* w_c2l2 = (const float*)d_in[10], *b_c2l2 = (const float*)d_in[11];
    const float* w_l2l1 = (const float*)d_in[12], *b_l2l1 = (const float*)d_in[13];
    const float* w_l2l2 = (const float*)d_in[14], *b_l2l2 = (const float*)d_in[15];
    const float* w_cu   = (const float*)d_in[16], *b_cu   = (const float*)d_in[17];
    const float* w_lu   = (const float*)d_in[18], *b_lu   = (const float*)d_in[19];
    (void)in_sizes; (void)n_in; (void)out_size;

    bf16 *lemb_h, *lemb_l, *cemb_h, *cemb_l, *l2l_h, *l2l_l;
    bf16 *agl_h, *agl_l, *agc_h, *agc_l;
    float *msg_l, *msg_c, *inv_l, *inv_c;
    int *cnt_l, *cnt_c, *off_l, *off_c, *adj_l, *adj_c, *cur_l, *cur_c;
    cudaGetSymbolAddress((void**)&lemb_h, g_lemb_h);
    cudaGetSymbolAddress((void**)&lemb_l, g_lemb_l);
    cudaGetSymbolAddress((void**)&cemb_h, g_cemb_h);
    cudaGetSymbolAddress((void**)&cemb_l, g_cemb_l);
    cudaGetSymbolAddress((void**)&l2l_h, g_l2l_h);
    cudaGetSymbolAddress((void**)&l2l_l, g_l2l_l);
    cudaGetSymbolAddress((void**)&agl_h, g_agl_h);
    cudaGetSymbolAddress((void**)&agl_l, g_agl_l);
    cudaGetSymbolAddress((void**)&agc_h, g_agc_h);
    cudaGetSymbolAddress((void**)&agc_l, g_agc_l);
    cudaGetSymbolAddress((void**)&msg_l, g_msg_l);
    cudaGetSymbolAddress((void**)&msg_c, g_msg_c);
    cudaGetSymbolAddress((void**)&inv_l, g_inv_l);
    cudaGetSymbolAddress((void**)&inv_c, g_inv_c);
    cudaGetSymbolAddress((void**)&cnt_l, g_cnt_l);
    cudaGetSymbolAddress((void**)&cnt_c, g_cnt_c);
    cudaGetSymbolAddress((void**)&off_l, g_off_l);
    cudaGetSymbolAddress((void**)&off_c, g_off_c);
    cudaGetSymbolAddress((void**)&adj_l, g_adj_l);
    cudaGetSymbolAddress((void**)&adj_c, g_adj_c);
    cudaGetSymbolAddress((void**)&cur_l, g_cur_l);
    cudaGetSymbolAddress((void**)&cur_c, g_cur_c);

    cudaFuncSetAttribute(k_mlp_tc, cudaFuncAttributeMaxDynamicSharedMemorySize, SMEM_MLP);
    cudaFuncSetAttribute(k_upd_tc, cudaFuncAttributeMaxDynamicSharedMemorySize, SMEM_UPD);

    // ---- graph construction ----
    cudaMemsetAsync(cnt_l, 0, L_SIZE * sizeof(int));
    cudaMemsetAsync(cnt_c, 0, C_SIZE * sizeof(int));
    k_detect<<<1, 256>>>((const unsigned*)l_ei);
    k_hist<<<E_SIZE / 256, 256>>>(l_ei, c_ei);
    k_bsum<<<L_SIZE / 1024, 256>>>(cnt_l);
    k_scan_base<<<1, 1>>>(L_SIZE / 1024);
    k_scan_write<<<L_SIZE / 1024, 256>>>(cnt_l, off_l, cur_l);
    k_bsum<<<C_SIZE / 1024, 256>>>(cnt_c);
    k_scan_base<<<1, 1>>>(C_SIZE / 1024);
    k_scan_write<<<C_SIZE / 1024, 256>>>(cnt_c, off_c, cur_c);
    k_fill<<<E_SIZE / 256, 256>>>(l_ei, c_ei);
    k_inv<<<L_SIZE / 256, 256>>>();

    // ---- weight images + embedding init ----
    k_wprep<<<22, 256>>>(w_l2c1, w_l2c2, w_c2l1, w_c2l2, w_l2l1, w_l2l2, w_cu, w_lu);
    k_init2<<<(L_SIZE * 16) / 256, 256>>>(lemb_h, lemb_l, l_init, L_SIZE * 16);
    k_init2<<<(C_SIZE * 16) / 256, 256>>>(cemb_h, cemb_l, c_init, C_SIZE * 16);

    // ---- message-passing iterations ----
    for (int it = 0; it < N_ITERS; it++) {
        k_mlp_tc<<<L_SIZE / 128, 256, SMEM_MLP>>>(lemb_h, lemb_l, 0, 2, b_l2c1, b_l2c2,
                                                  inv_l, msg_l, nullptr, nullptr, 0);
        k_mlp_tc<<<C_SIZE / 128, 256, SMEM_MLP>>>(cemb_h, cemb_l, 4, 6, b_c2l1, b_c2l2,
                                                  inv_c, msg_c, nullptr, nullptr, 0);
        k_mlp_tc<<<L_SIZE / 128, 256, SMEM_MLP>>>(lemb_h, lemb_l, 8, 10, b_l2l1, b_l2l2,
                                                  nullptr, nullptr, l2l_h, l2l_l, 1);

        k_aggr<<<C_SIZE / 8, 256>>>(msg_l, adj_c, off_c, cnt_c, inv_c, agc_h, agc_l, C_SIZE);
        k_upd_tc<<<C_SIZE / 128, 256, SMEM_UPD>>>(cemb_h, cemb_l, agc_h, agc_l,
                                                  nullptr, nullptr, 12, b_cu,
                                                  cemb_h, cemb_l, nullptr, 2);

        k_aggr<<<L_SIZE / 8, 256>>>(msg_c, adj_l, off_l, cnt_l, inv_l, agl_h, agl_l, L_SIZE);
        float* fo = (it == N_ITERS - 1) ? (float*)d_out : nullptr;
        k_upd_tc<<<L_SIZE / 128, 256, SMEM_UPD>>>(lemb_h, lemb_l, agl_h, agl_l,
                                                  l2l_h, l2l_l, 16, b_lu,
                                                  lemb_h, lemb_l, fo, 3);
    }
}

// round 9
// speedup vs baseline: 1.9879x; 1.0148x over previous
#include <cuda_runtime.h>
#include <cuda_bf16.h>
#include <cstdint>

#define L_SIZE 65536
#define C_SIZE 32768
#define E_SIZE 262144
#define D 128
#define N_ITERS 4
#define NL_CTA (L_SIZE / 128)   // 512
#define NC_CTA (C_SIZE / 128)   // 256

using bf16 = __nv_bfloat16;

// ================= device scratch =================
__device__ __align__(16) bf16 g_lemb_h[(size_t)L_SIZE * D];
__device__ __align__(16) bf16 g_lemb_l[(size_t)L_SIZE * D];
__device__ __align__(16) bf16 g_cemb_h[(size_t)C_SIZE * D];
__device__ __align__(16) bf16 g_cemb_l[(size_t)C_SIZE * D];
__device__ __align__(16) float g_msg_l[(size_t)L_SIZE * D];
__device__ __align__(16) float g_msg_c[(size_t)C_SIZE * D];
__device__ __align__(16) bf16 g_l2l_h[(size_t)L_SIZE * D];
__device__ __align__(16) bf16 g_l2l_l[(size_t)L_SIZE * D];
__device__ __align__(16) bf16 g_agl_h[(size_t)L_SIZE * D];
__device__ __align__(16) bf16 g_agl_l[(size_t)L_SIZE * D];
__device__ __align__(16) bf16 g_agc_h[(size_t)C_SIZE * D];
__device__ __align__(16) bf16 g_agc_l[(size_t)C_SIZE * D];
__device__ __align__(16) bf16 g_wimg_h[22 * 8192];
__device__ __align__(16) bf16 g_wimg_l[22 * 8192];
__device__ int   g_cnt_l[L_SIZE], g_cnt_c[C_SIZE];
__device__ int   g_off_l[L_SIZE], g_off_c[C_SIZE];
__device__ int   g_cur_l[L_SIZE], g_cur_c[C_SIZE];
__device__ int   g_adj_c[E_SIZE];
__device__ int   g_adj_l[E_SIZE];
__device__ float g_inv_l[L_SIZE], g_inv_c[C_SIZE];
__device__ int   g_bsum[96];
__device__ int   g_idx64;

// ================= helpers =================
__device__ __forceinline__ uint32_t smem_u32(const void* p) {
    uint32_t a;
    asm("{ .reg .u64 t; cvta.to.shared.u64 t, %1; cvt.u32.u64 %0, t; }" : "=r"(a) : "l"(p));
    return a;
}
__device__ __forceinline__ int swz(int off) { return off ^ ((off >> 3) & 0x70); }

__device__ __forceinline__ void split_bf(float v, unsigned short& h, unsigned short& l) {
    bf16 hb = __float2bfloat16_rn(v);
    bf16 lb = __float2bfloat16_rn(v - __bfloat162float(hb));
    h = __bfloat16_as_ushort(hb);
    l = __bfloat16_as_ushort(lb);
}

__device__ __forceinline__ void ldmx4(uint32_t* r, uint32_t addr) {
    asm volatile("ldmatrix.sync.aligned.m8n8.x4.shared.b16 {%0,%1,%2,%3}, [%4];"
                 : "=r"(r[0]), "=r"(r[1]), "=r"(r[2]), "=r"(r[3]) : "r"(addr));
}

__device__ __forceinline__ void mma16816(float (&c)[4], const uint32_t* a, const uint32_t* b) {
    asm volatile(
        "mma.sync.aligned.m16n8k16.row.col.f32.bf16.bf16.f32 "
        "{%0,%1,%2,%3}, {%4,%5,%6,%7}, {%8,%9}, {%0,%1,%2,%3};"
        : "+f"(c[0]), "+f"(c[1]), "+f"(c[2]), "+f"(c[3])
        : "r"(a[0]), "r"(a[1]), "r"(a[2]), "r"(a[3]), "r"(b[0]), "r"(b[1]));
}

__device__ __forceinline__ void cpa16(uint32_t dst, const void* src) {
    asm volatile("cp.async.cg.shared.global [%0], [%1], 16;" :: "r"(dst), "l"(src) : "memory");
}
#define CP_COMMIT() asm volatile("cp.async.commit_group;" ::: "memory")
#define CP_WAIT(n)  asm volatile("cp.async.wait_group %0;" :: "n"(n) : "memory")

// ===== SMEM maps (bytes) =====
// MLP: bias[512f]@0; A@2048 (64K); H@67584 (64K); W-ring @133120 (3 x 32K). total 231424.
//      fp32 stage (128x128 col-rotated) overlays H.
#define M_A  2048
#define M_H  67584
#define M_W  133120
#define SMEM_MLP 231424
// UPD: bias@0; 3 slots @2048, each 64K = [Ah|Al|Wh|Wl]. stage overlays slot0.
#define U_SL 2048
#define SMEM_UPD (2048 + 3 * 65536)

// ================= edge-index dtype handling =================
__device__ __forceinline__ int eidx(const void* p, int i, int f) {
    if (f) return (int)((const unsigned long long*)p)[i];
    return ((const int*)p)[i];
}
__global__ void k_detect(const unsigned* p) {
    unsigned v = p[2 * threadIdx.x + 1];
    __shared__ int anynz;
    if (threadIdx.x == 0) anynz = 0;
    __syncthreads();
    unsigned b = __ballot_sync(0xffffffffu, v != 0u);
    if ((threadIdx.x & 31) == 0 && b) atomicExch(&anynz, 1);
    __syncthreads();
    if (threadIdx.x == 0) g_idx64 = (anynz == 0) ? 1 : 0;
}
__global__ void k_hist(const void* lp, const void* cp) {
    int e = blockIdx.x * blockDim.x + threadIdx.x;
    int f = g_idx64;
    atomicAdd(&g_cnt_l[eidx(lp, e, f)], 1);
    atomicAdd(&g_cnt_c[eidx(cp, e, f)], 1);
}
// merged block sums: blocks 0..63 -> cnt_l, 64..95 -> cnt_c
__global__ void k_bsum_all() {
    __shared__ int sh[256];
    const int* cnt = (blockIdx.x < 64) ? g_cnt_l : g_cnt_c;
    int rel = (blockIdx.x < 64) ? blockIdx.x : blockIdx.x - 64;
    int base = rel * 1024 + threadIdx.x;
    int s = 0;
#pragma unroll
    for (int t = 0; t < 4; t++) s += cnt[base + t * 256];
    sh[threadIdx.x] = s;
    __syncthreads();
    for (int o = 128; o > 0; o >>= 1) {
        if (threadIdx.x < o) sh[threadIdx.x] += sh[threadIdx.x + o];
        __syncthreads();
    }
    if (threadIdx.x == 0) g_bsum[blockIdx.x] = sh[0];
}
// merged scan+write: per-block prefix over g_bsum computed in-block
__global__ void k_scanw_all() {
    __shared__ int sh[256];
    __shared__ int sb[64];
    int tid = threadIdx.x;
    int isl = blockIdx.x < 64;
    int lo = isl ? 0 : 64;
    int rel = blockIdx.x - lo;
    const int* cnt = isl ? g_cnt_l : g_cnt_c;
    int* off = isl ? g_off_l : g_off_c;
    int* cur = isl ? g_cur_l : g_cur_c;

    if (tid < 64) sb[tid] = (tid < rel) ? g_bsum[lo + tid] : 0;
    __syncthreads();
    for (int o = 32; o > 0; o >>= 1) {
        if (tid < o) sb[tid] += sb[tid + o];
        __syncthreads();
    }
    int base = sb[0];

    int base4 = rel * 1024 + tid * 4;
    int4 v = *(const int4*)(cnt + base4);
    int tsum = v.x + v.y + v.z + v.w;
    sh[tid] = tsum;
    __syncthreads();
    for (int o = 1; o < 256; o <<= 1) {
        int t = (tid >= o) ? sh[tid - o] : 0;
        __syncthreads();
        sh[tid] += t;
        __syncthreads();
    }
    int e = base + sh[tid] - tsum;
    off[base4 + 0] = e; cur[base4 + 0] = e; e += v.x;
    off[base4 + 1] = e; cur[base4 + 1] = e; e += v.y;
    off[base4 + 2] = e; cur[base4 + 2] = e; e += v.z;
    off[base4 + 3] = e; cur[base4 + 3] = e;
}
__global__ void k_fill(const void* lp, const void* cp) {
    int e = blockIdx.x * blockDim.x + threadIdx.x;
    int f = g_idx64;
    int li = eidx(lp, e, f);
    int ci = eidx(cp, e, f);
    g_adj_c[atomicAdd(&g_cur_c[ci], 1)] = li;
    g_adj_l[atomicAdd(&g_cur_l[li], 1)] = ci;
}
__global__ void k_inv() {
    int i = blockIdx.x * blockDim.x + threadIdx.x;
    if (i < L_SIZE) { int c = g_cnt_l[i]; g_inv_l[i] = c ? rsqrtf((float)c) : 0.0f; }
    if (i < C_SIZE) { int c = g_cnt_c[i]; g_inv_c[i] = c ? rsqrtf((float)c) : 0.0f; }
}

// ================= init / weight prep =================
__global__ void k_init_all(const float* __restrict__ l_init, const float* __restrict__ c_init) {
    int i = blockIdx.x * blockDim.x + threadIdx.x;           // (L+C)*16 threads
    bf16 *dh, *dl;
    const float* init;
    int rel;
    if (i < L_SIZE * 16) { dh = g_lemb_h; dl = g_lemb_l; init = l_init; rel = i; }
    else { dh = g_cemb_h; dl = g_cemb_l; init = c_init; rel = i - L_SIZE * 16; }
    int c8 = (rel & 15) * 8;
    size_t base = (size_t)(rel >> 4) * 128 + c8;
    unsigned short hh[8], ll[8];
#pragma unroll
    for (int j = 0; j < 8; j++) split_bf(init[c8 + j], hh[j], ll[j]);
    uint4 H, L;
    H.x = hh[0] | ((uint32_t)hh[1] << 16); H.y = hh[2] | ((uint32_t)hh[3] << 16);
    H.z = hh[4] | ((uint32_t)hh[5] << 16); H.w = hh[6] | ((uint32_t)hh[7] << 16);
    L.x = ll[0] | ((uint32_t)ll[1] << 16); L.y = ll[2] | ((uint32_t)ll[3] << 16);
    L.z = ll[4] | ((uint32_t)ll[5] << 16); L.w = ll[6] | ((uint32_t)ll[7] << 16);
    *(uint4*)(dh + base) = H;
    *(uint4*)(dl + base) = L;
}

// image `half` holds Bt[n][k] = W[k0+k][n], n in [0,128), k in [0,64), SW128-swizzled.
__global__ void k_wprep(const float* w0, const float* w1, const float* w2, const float* w3,
                        const float* w4, const float* w5, const float* wcu, const float* wlu) {
    int half = blockIdx.x;
    const float* W;
    int k0;
    if (half < 12) {
        const float* ws[6] = {w0, w1, w2, w3, w4, w5};
        W = ws[half >> 1];
        k0 = (half & 1) * 64;
    } else if (half < 16) {
        W = wcu; k0 = (half - 12) * 64;
    } else {
        W = wlu; k0 = (half - 16) * 64;
    }
    bf16* oh = g_wimg_h + (size_t)half * 8192;
    bf16* ol = g_wimg_l + (size_t)half * 8192;
    for (int idx = threadIdx.x; idx < 8192; idx += blockDim.x) {
        int n = idx >> 6, k = idx & 63;
        float v = W[(size_t)(k0 + k) * 128 + n];
        unsigned short h, l;
        split_bf(v, h, l);
        int sw = swz(n * 128 + k * 2);
        *(unsigned short*)((char*)oh + sw) = h;
        *(unsigned short*)((char*)ol + sw) = l;
    }
}

// ================= async tile fills =================
__device__ __forceinline__ void issue_A_full(uint32_t a_base, const bf16* __restrict__ Xh,
                                             const bf16* __restrict__ Xl, size_t rowbase, int tid) {
    for (int i = tid; i < 2048; i += 256) {
        int row = i >> 4, u = i & 15;
        int half = u >> 3, uu = u & 7;
        size_t goff = (rowbase + row) * 128 + u * 8;
        uint32_t d = a_base + half * 32768 + swz(row * 128 + uu * 16);
        cpa16(d, Xh + goff);
        cpa16(d + 16384, Xl + goff);
    }
}
// one 32K W slot: [hi 16K | lo 16K] from pre-swizzled image
__device__ __forceinline__ void issue_W(uint32_t slot, int wimg, int tid) {
    const uint4* sh = (const uint4*)(g_wimg_h + (size_t)wimg * 8192);
    const uint4* sl = (const uint4*)(g_wimg_l + (size_t)wimg * 8192);
    for (int i = tid; i < 1024; i += 256) {
        cpa16(slot + i * 16, sh + i);
        cpa16(slot + 16384 + i * 16, sl + i);
    }
}
// one K=64 upd slot: [Ah|Al|Wh|Wl]
__device__ __forceinline__ void issue_half(uint32_t slot, const bf16* __restrict__ Sh,
                                           const bf16* __restrict__ Sl, size_t rowbase,
                                           int k64, int wimg, int tid) {
    for (int i = tid; i < 1024; i += 256) {
        int row = i >> 3, uu = i & 7;
        size_t goff = (rowbase + row) * 128 + k64 * 64 + uu * 8;
        uint32_t d = slot + swz(row * 128 + uu * 16);
        cpa16(d, Sh + goff);
        cpa16(d + 16384, Sl + goff);
        cpa16(slot + 32768 + i * 16, (const uint4*)(g_wimg_h + (size_t)wimg * 8192) + i);
        cpa16(slot + 49152 + i * 16, (const uint4*)(g_wimg_l + (size_t)wimg * 8192) + i);
    }
}

// ================= warp GEMM over one K=64 half (3-term hi/lo split) =================
// warp (wid>>1) owns rows [(wid>>1)*32,+32); (wid&1) owns cols [(wid&1)*64,+64)
__device__ __forceinline__ void warp_mma_k64(float (&acc)[16][4], uint32_t a_base,
                                             uint32_t w_base, int lane, int wid, int rxor) {
    const int wrow0 = (wid >> 1) * 32;
    const int nbase = (wid & 1) * 64;
#pragma unroll
    for (int kc = 0; kc < 4; kc++) {
        int kb = kc * 32;
        uint32_t ah[8], al[8];
#pragma unroll
        for (int mt = 0; mt < 2; mt++) {
            int arow = (wrow0 + mt * 16 + (lane & 15)) ^ rxor;
            int acol = kb + ((lane >> 4) << 4);
            uint32_t aaddr = a_base + swz(arow * 128 + acol);
            ldmx4(ah + mt * 4, aaddr);
            ldmx4(al + mt * 4, aaddr + 16384);
        }
        int brow = (lane & 7) + ((lane >> 4) & 1) * 8;
        int bcol = kb + (((lane >> 3) & 1) << 4);
        uint32_t bh[16], bl[16];
#pragma unroll
        for (int gg = 0; gg < 4; gg++) {
            uint32_t baddr = w_base + swz((nbase + gg * 16 + brow) * 128 + bcol);
            ldmx4(bh + gg * 4, baddr);
            ldmx4(bl + gg * 4, baddr + 16384);
        }
#pragma unroll
        for (int term = 0; term < 3; term++) {
            const uint32_t* A = (term == 2) ? al : ah;
            const uint32_t* B = (term == 1) ? bl : bh;
#pragma unroll
            for (int mt = 0; mt < 2; mt++)
#pragma unroll
                for (int t = 0; t < 8; t++)
                    mma16816(acc[mt * 8 + t], A + mt * 4, B + (t >> 1) * 4 + (t & 1) * 2);
        }
    }
}

// fragment -> relu/bias -> split -> H region
__device__ __forceinline__ void store_H(char* hbase, float (&acc)[16][4],
                                        const float* __restrict__ b1s, int lane, int wid) {
    const int wrow0 = (wid >> 1) * 32;
    const int nbase = (wid & 1) * 64;
    int g = lane >> 2, tig = lane & 3;
#pragma unroll
    for (int mt = 0; mt < 2; mt++)
#pragma unroll
        for (int nt = 0; nt < 8; nt++) {
            int n = nbase + nt * 8 + 2 * tig;
            int half = n >> 6, kk = n & 63;
            float bz0 = b1s[n], bz1 = b1s[n + 1];
            const float* a = acc[mt * 8 + nt];
            int r0 = wrow0 + mt * 16 + g, r1 = r0 + 8;
            float v00 = fmaxf(a[0] + bz0, 0.0f), v01 = fmaxf(a[1] + bz1, 0.0f);
            float v10 = fmaxf(a[2] + bz0, 0.0f), v11 = fmaxf(a[3] + bz1, 0.0f);
            unsigned short h00, l00, h01, l01, h10, l10, h11, l11;
            split_bf(v00, h00, l00); split_bf(v01, h01, l01);
            split_bf(v10, h10, l10); split_bf(v11, h11, l11);
            char* dh = hbase + half * 32768;
            char* dl = dh + 16384;
            int sw0 = swz(r0 * 128 + kk * 2), sw1 = swz(r1 * 128 + kk * 2);
            *(uint32_t*)(dh + sw0) = h00 | ((uint32_t)h01 << 16);
            *(uint32_t*)(dl + sw0) = l00 | ((uint32_t)l01 << 16);
            *(uint32_t*)(dh + sw1) = h10 | ((uint32_t)h11 << 16);
            *(uint32_t*)(dl + sw1) = l10 | ((uint32_t)l11 << 16);
        }
}

// fragment -> bias -> col-rotated fp32 stage (stride 128, col' = (col + 4*row) & 127)
__device__ __forceinline__ void acc_to_stage(float* __restrict__ stage, float (&acc)[16][4],
                                             const float* __restrict__ bs, int lane, int wid) {
    const int wrow0 = (wid >> 1) * 32;
    const int nbase = (wid & 1) * 64;
    int g = lane >> 2, tig = lane & 3;
#pragma unroll
    for (int mt = 0; mt < 2; mt++)
#pragma unroll
        for (int nt = 0; nt < 8; nt++) {
            int n = nbase + nt * 8 + 2 * tig;
            float bz0 = bs[n], bz1 = bs[n + 1];
            const float* a = acc[mt * 8 + nt];
            int r0 = wrow0 + mt * 16 + g, r1 = r0 + 8;
            int c0 = (n + 4 * r0) & 127, c1 = (n + 4 * r1) & 127;
            *(float2*)(stage + r0 * 128 + c0) = make_float2(a[0] + bz0, a[1] + bz1);
            *(float2*)(stage + r1 * 128 + c1) = make_float2(a[2] + bz0, a[3] + bz1);
        }
}

// staged epilogue: col-rotated smem fp32 -> gmem
__device__ __forceinline__ void epilogue_writer(
    const float* __restrict__ stage, size_t rowbase,
    const float* __restrict__ inv, float* __restrict__ outf,
    bf16* __restrict__ outh, bf16* __restrict__ outl, int tid) {
    int r = tid >> 1, h = tid & 1;
    size_t grow = rowbase + r;
    const float* srow = stage + r * 128;
    int rot = 4 * r;
    if (outf) {
        float sc = inv ? inv[grow] : 1.0f;
        float4* of = (float4*)(outf + grow * 128 + h * 64);
#pragma unroll
        for (int u = 0; u < 16; u++) {
            float4 v = *(const float4*)(srow + ((h * 64 + u * 4 + rot) & 127));
            v.x *= sc; v.y *= sc; v.z *= sc; v.w *= sc;
            of[u] = v;
        }
    }
    if (outh) {
        uint4* oh = (uint4*)(outh + grow * 128 + h * 64);
        uint4* ol = (uint4*)(outl + grow * 128 + h * 64);
#pragma unroll
        for (int u = 0; u < 8; u++) {
            float4 a = *(const float4*)(srow + ((h * 64 + u * 8 + rot) & 127));
            float4 b = *(const float4*)(srow + ((h * 64 + u * 8 + 4 + rot) & 127));
            unsigned short hh[8], ll[8];
            split_bf(a.x, hh[0], ll[0]); split_bf(a.y, hh[1], ll[1]);
            split_bf(a.z, hh[2], ll[2]); split_bf(a.w, hh[3], ll[3]);
            split_bf(b.x, hh[4], ll[4]); split_bf(b.y, hh[5], ll[5]);
            split_bf(b.z, hh[6], ll[6]); split_bf(b.w, hh[7], ll[7]);
            uint4 H, L;
            H.x = hh[0] | ((uint32_t)hh[1] << 16); H.y = hh[2] | ((uint32_t)hh[3] << 16);
            H.z = hh[4] | ((uint32_t)hh[5] << 16); H.w = hh[6] | ((uint32_t)hh[7] << 16);
            L.x = ll[0] | ((uint32_t)ll[1] << 16); L.y = ll[2] | ((uint32_t)ll[3] << 16);
            L.z = ll[4] | ((uint32_t)ll[5] << 16); L.w = ll[6] | ((uint32_t)ll[7] << 16);
            oh[u] = H;
            ol[u] = L;
        }
    }
}

#define ZERO_ACC(acc) do {                       \
    _Pragma("unroll")                            \
    for (int t_ = 0; t_ < 16; t_++)              \
        _Pragma("unroll")                        \
        for (int j_ = 0; j_ < 4; j_++) (acc)[t_][j_] = 0.0f; } while (0)

// ================= mega MLP kernel: all 3 MLPs in one launch =================
// bid < 512: L task (l2c then l2l, shared A). bid >= 512: C task (c2l).
__global__ __launch_bounds__(256, 1) void k_mlp_all(
    const bf16* __restrict__ lemb_h, const bf16* __restrict__ lemb_l,
    const bf16* __restrict__ cemb_h, const bf16* __restrict__ cemb_l,
    const float* __restrict__ b_l2c1, const float* __restrict__ b_l2c2,
    const float* __restrict__ b_c2l1, const float* __restrict__ b_c2l2,
    const float* __restrict__ b_l2l1, const float* __restrict__ b_l2l2,
    const float* __restrict__ inv_l, const float* __restrict__ inv_c,
    float* __restrict__ msg_l, float* __restrict__ msg_c,
    bf16* __restrict__ l2l_h, bf16* __restrict__ l2l_l) {
    extern __shared__ __align__(1024) char sm[];
    uint32_t smem_base = smem_u32(sm);
    float* bs = (float*)sm;
    float* stage = (float*)(sm + M_H);
    int tid = threadIdx.x, wid = tid >> 5, lane = tid & 31;
    int bid = blockIdx.x;
    bool isL = bid < NL_CTA;
    size_t rowbase = isL ? (size_t)bid * 128 : (size_t)(bid - NL_CTA) * 128;
    const bf16* Xh = isL ? lemb_h : cemb_h;
    const bf16* Xl = isL ? lemb_l : cemb_l;
    int nstep = isL ? 8 : 4;

    // bias staging
    if (isL) {
        for (int i = tid; i < 512; i += 256) {
            float v;
            if (i < 128) v = b_l2c1[i];
            else if (i < 256) v = b_l2c2[i - 128];
            else if (i < 384) v = b_l2l1[i - 256];
            else v = b_l2l2[i - 384];
            bs[i] = v;
        }
    } else {
        bs[tid] = (tid < 128) ? b_c2l1[tid] : b_c2l2[tid - 128];
    }

    uint32_t AB = smem_base + M_A, HB = smem_base + M_H, WB = smem_base + M_W;
    // prologue: A + first 3 W slots
    issue_A_full(AB, Xh, Xl, rowbase, tid);
    issue_W(WB, isL ? 0 : 4, tid);
    CP_COMMIT();
    issue_W(WB + 32768, isL ? 1 : 5, tid);
    CP_COMMIT();
    issue_W(WB + 65536, isL ? 2 : 6, tid);
    CP_COMMIT();

    float acc[16][4];
    ZERO_ACC(acc);

#pragma unroll 1
    for (int j = 0; j < nstep; j++) {
        if (j == 0) CP_WAIT(2);
        else if (j == nstep - 1) CP_WAIT(0);
        else CP_WAIT(1);
        __syncthreads();
        if (j >= 1 && j + 2 < nstep) {
            int im = j + 2;
            int wimg = isL ? (im < 4 ? im : im + 4) : (4 + im);
            issue_W(WB + ((im % 3) * 32768), wimg, tid);
            CP_COMMIT();
        }
        int ph = j >> 1;
        bool p2 = (ph & 1) != 0;
        uint32_t abase = (p2 ? HB : AB) + (j & 1) * 32768;
        int rxor = (isL && ph == 2) ? 1 : 0;
        warp_mma_k64(acc, abase, WB + (j % 3) * 32768, lane, wid, rxor);

        if (j & 1) {
            if (!p2) {
                // finished phase 1: relu+split into H
                store_H(sm + M_H, acc, bs + ((ph >> 1) * 256), lane, wid);
                ZERO_ACC(acc);
            } else {
                // finished phase 2: epilogue (stage overlays H; H reads done after sync)
                __syncthreads();
                acc_to_stage(stage, acc, bs + 128 + ((ph >> 1) * 256), lane, wid);
                __syncthreads();
                if (!isL)
                    epilogue_writer(stage, rowbase, inv_c, msg_c, nullptr, nullptr, tid);
                else if (ph == 1)
                    epilogue_writer(stage, rowbase, inv_l, msg_l, nullptr, nullptr, tid);
                else
                    epilogue_writer(stage, rowbase, nullptr, nullptr, l2l_h, l2l_l, tid);
                ZERO_ACC(acc);
            }
        }
    }
}

// ================= mega update kernel: updL + updC in one launch =================
__global__ __launch_bounds__(256, 1) void k_upd_all(
    const bf16* __restrict__ lemb_h, const bf16* __restrict__ lemb_l,
    const bf16* __restrict__ agl_h, const bf16* __restrict__ agl_l,
    const bf16* __restrict__ l2l_h, const bf16* __restrict__ l2l_l,
    const bf16* __restrict__ cemb_h, const bf16* __restrict__ cemb_l,
    const bf16* __restrict__ agc_h, const bf16* __restrict__ agc_l,
    const float* __restrict__ b_lu, const float* __restrict__ b_cu,
    bf16* __restrict__ olemb_h, bf16* __restrict__ olemb_l,
    bf16* __restrict__ ocemb_h, bf16* __restrict__ ocemb_l,
    float* __restrict__ fo) {
    extern __shared__ __align__(1024) char sm[];
    uint32_t smem_base = smem_u32(sm);
    float* bs = (float*)sm;
    float* stage = (float*)(sm + U_SL);
    int tid = threadIdx.x, wid = tid >> 5, lane = tid & 31;
    int bid = blockIdx.x;
    bool isL = bid < NL_CTA;
    size_t rowbase = isL ? (size_t)bid * 128 : (size_t)(bid - NL_CTA) * 128;
    int H = isL ? 6 : 4;
    int whalf = isL ? 16 : 12;

    if (tid < 128) bs[tid] = isL ? b_lu[tid] : b_cu[tid];

    const bf16* Sh[3];
    const bf16* Sl[3];
    if (isL) { Sh[0] = lemb_h; Sl[0] = lemb_l; Sh[1] = agl_h; Sl[1] = agl_l; Sh[2] = l2l_h; Sl[2] = l2l_l; }
    else { Sh[0] = cemb_h; Sl[0] = cemb_l; Sh[1] = agc_h; Sl[1] = agc_l; Sh[2] = cemb_h; Sl[2] = cemb_l; }

    // prologue: first 3 half-slots
#pragma unroll
    for (int s = 0; s < 3; s++) {
        int c = s >> 1;
        issue_half(smem_base + U_SL + s * 65536, Sh[c], Sl[c], rowbase, s & 1, whalf + s, tid);
        CP_COMMIT();
    }

    float acc[16][4];
    ZERO_ACC(acc);

#pragma unroll 1
    for (int h = 0; h < H; h++) {
        if (h == 0) CP_WAIT(2);
        else if (h == H - 1) CP_WAIT(0);
        else CP_WAIT(1);
        __syncthreads();
        if (h >= 1 && h + 2 < H) {
            int s = h + 2;
            int c = s >> 1;
            issue_half(smem_base + U_SL + (s % 3) * 65536, Sh[c], Sl[c], rowbase,
                       s & 1, whalf + s, tid);
            CP_COMMIT();
        }
        uint32_t slot = smem_base + U_SL + (h % 3) * 65536;
        warp_mma_k64(acc, slot, slot + 32768, lane, wid, 0);
    }
    __syncthreads();
    acc_to_stage(stage, acc, bs, lane, wid);
    __syncthreads();
    if (isL) epilogue_writer(stage, rowbase, nullptr, fo, olemb_h, olemb_l, tid);
    else epilogue_writer(stage, rowbase, nullptr, nullptr, ocemb_h, ocemb_l, tid);
}

// ================= merged CSR aggregation (C then L) -> hi/lo bf16 =================
__global__ void k_aggr_all(const float* __restrict__ msg_l, const float* __restrict__ msg_c) {
    int w = blockIdx.x * 8 + (threadIdx.x >> 5);
    int lane = threadIdx.x & 31;
    const float* msg;
    const int *adj, *off, *cnt;
    const float* inv;
    bf16 *outh, *outl;
    int node;
    if (w < C_SIZE) {
        node = w; msg = msg_l; adj = g_adj_c; off = g_off_c; cnt = g_cnt_c;
        inv = g_inv_c; outh = g_agc_h; outl = g_agc_l;
    } else {
        node = w - C_SIZE; msg = msg_c; adj = g_adj_l; off = g_off_l; cnt = g_cnt_l;
        inv = g_inv_l; outh = g_agl_h; outl = g_agl_l;
    }
    int o = off[node], d = cnt[node];
    float4 acc = make_float4(0.f, 0.f, 0.f, 0.f);
    float4 acc2 = make_float4(0.f, 0.f, 0.f, 0.f);
    int j = 0;
    for (; j + 2 <= d; j += 2) {
        int s0 = adj[o + j], s1 = adj[o + j + 1];
        float4 v0 = *(const float4*)(msg + (size_t)s0 * D + lane * 4);
        float4 v1 = *(const float4*)(msg + (size_t)s1 * D + lane * 4);
        acc.x += v0.x; acc.y += v0.y; acc.z += v0.z; acc.w += v0.w;
        acc2.x += v1.x; acc2.y += v1.y; acc2.z += v1.z; acc2.w += v1.w;
    }
    if (j < d) {
        int s0 = adj[o + j];
        float4 v0 = *(const float4*)(msg + (size_t)s0 * D + lane * 4);
        acc.x += v0.x; acc.y += v0.y; acc.z += v0.z; acc.w += v0.w;
    }
    acc.x += acc2.x; acc.y += acc2.y; acc.z += acc2.z; acc.w += acc2.w;
    float sc = inv[node];
    acc.x *= sc; acc.y *= sc; acc.z *= sc; acc.w *= sc;
    unsigned short hh[4], ll[4];
    split_bf(acc.x, hh[0], ll[0]); split_bf(acc.y, hh[1], ll[1]);
    split_bf(acc.z, hh[2], ll[2]); split_bf(acc.w, hh[3], ll[3]);
    uint2 Hh, Ll;
    Hh.x = hh[0] | ((uint32_t)hh[1] << 16); Hh.y = hh[2] | ((uint32_t)hh[3] << 16);
    Ll.x = ll[0] | ((uint32_t)ll[1] << 16); Ll.y = ll[2] | ((uint32_t)ll[3] << 16);
    *(uint2*)(outh + (size_t)node * D + lane * 4) = Hh;
    *(uint2*)(outl + (size_t)node * D + lane * 4) = Ll;
}

// ================= host launcher =================
extern "C" void kernel_launch(void* const* d_in, const int* in_sizes, int n_in,
                              void* d_out, int out_size) {
    const void* l_ei = d_in[0];
    const void* c_ei = d_in[1];
    const float* l_init = (const float*)d_in[2];
    const float* c_init = (const float*)d_in[3];
    const float* w_l2c1 = (const float*)d_in[4],  *b_l2c1 = (const float*)d_in[5];
    const float* w_l2c2 = (const float*)d_in[6],  *b_l2c2 = (const float*)d_in[7];
    const float* w_c2l1 = (const float*)d_in[8],  *b_c2l1 = (const float*)d_in[9];
    const float* w_c2l2 = (const float*)d_in[10], *b_c2l2 = (const float*)d_in[11];
    const float* w_l2l1 = (const float*)d_in[12], *b_l2l1 = (const float*)d_in[13];
    const float* w_l2l2 = (const float*)d_in[14], *b_l2l2 = (const float*)d_in[15];
    const float* w_cu   = (const float*)d_in[16], *b_cu   = (const float*)d_in[17];
    const float* w_lu   = (const float*)d_in[18], *b_lu   = (const float*)d_in[19];
    (void)in_sizes; (void)n_in; (void)out_size;

    bf16 *lemb_h, *lemb_l, *cemb_h, *cemb_l, *l2l_h, *l2l_l;
    bf16 *agl_h, *agl_l, *agc_h, *agc_l;
    float *msg_l, *msg_c, *inv_l, *inv_c;
    int *cnt_l, *cnt_c;
    cudaGetSymbolAddress((void**)&lemb_h, g_lemb_h);
    cudaGetSymbolAddress((void**)&lemb_l, g_lemb_l);
    cudaGetSymbolAddress((void**)&cemb_h, g_cemb_h);
    cudaGetSymbolAddress((void**)&cemb_l, g_cemb_l);
    cudaGetSymbolAddress((void**)&l2l_h, g_l2l_h);
    cudaGetSymbolAddress((void**)&l2l_l, g_l2l_l);
    cudaGetSymbolAddress((void**)&agl_h, g_agl_h);
    cudaGetSymbolAddress((void**)&agl_l, g_agl_l);
    cudaGetSymbolAddress((void**)&agc_h, g_agc_h);
    cudaGetSymbolAddress((void**)&agc_l, g_agc_l);
    cudaGetSymbolAddress((void**)&msg_l, g_msg_l);
    cudaGetSymbolAddress((void**)&msg_c, g_msg_c);
    cudaGetSymbolAddress((void**)&inv_l, g_inv_l);
    cudaGetSymbolAddress((void**)&inv_c, g_inv_c);
    cudaGetSymbolAddress((void**)&cnt_l, g_cnt_l);
    cudaGetSymbolAddress((void**)&cnt_c, g_cnt_c);

    cudaFuncSetAttribute(k_mlp_all, cudaFuncAttributeMaxDynamicSharedMemorySize, SMEM_MLP);
    cudaFuncSetAttribute(k_upd_all, cudaFuncAttributeMaxDynamicSharedMemorySize, SMEM_UPD);

    // ---- graph construction ----
    cudaMemsetAsync(cnt_l, 0, L_SIZE * sizeof(int));
    cudaMemsetAsync(cnt_c, 0, C_SIZE * sizeof(int));
    k_detect<<<1, 256>>>((const unsigned*)l_ei);
    k_hist<<<E_SIZE / 256, 256>>>(l_ei, c_ei);
    k_bsum_all<<<96, 256>>>();
    k_scanw_all<<<96, 256>>>();
    k_fill<<<E_SIZE / 256, 256>>>(l_ei, c_ei);
    k_inv<<<L_SIZE / 256, 256>>>();

    // ---- weight images + embedding init ----
    k_wprep<<<22, 256>>>(w_l2c1, w_l2c2, w_c2l1, w_c2l2, w_l2l1, w_l2l2, w_cu, w_lu);
    k_init_all<<<((L_SIZE + C_SIZE) * 16) / 256, 256>>>(l_init, c_init);

    // ---- message-passing iterations: 3 launches each ----
    for (int it = 0; it < N_ITERS; it++) {
        k_mlp_all<<<NL_CTA + NC_CTA, 256, SMEM_MLP>>>(
            lemb_h, lemb_l, cemb_h, cemb_l,
            b_l2c1, b_l2c2, b_c2l1, b_c2l2, b_l2l1, b_l2l2,
            inv_l, inv_c, msg_l, msg_c, l2l_h, l2l_l);

        k_aggr_all<<<(L_SIZE + C_SIZE) / 8, 256>>>(msg_l, msg_c);

        float* fo = (it == N_ITERS - 1) ? (float*)d_out : nullptr;
        k_upd_all<<<NL_CTA + NC_CTA, 256, SMEM_UPD>>>(
            lemb_h, lemb_l, agl_h, agl_l, l2l_h, l2l_l,
            cemb_h, cemb_l, agc_h, agc_l,
            b_lu, b_cu, lemb_h, lemb_l, cemb_h, cemb_l, fo);
    }
}

// round 10
// speedup vs baseline: 1.9992x; 1.0057x over previous
#include <cuda_runtime.h>
#include <cuda_bf16.h>
#include <cstdint>

#define L_SIZE 65536
#define C_SIZE 32768
#define E_SIZE 262144
#define D 128
#define N_ITERS 4
#define NL_CTA (L_SIZE / 128)   // 512
#define NC_CTA (C_SIZE / 128)   // 256

using bf16 = __nv_bfloat16;

// ================= device scratch =================
__device__ __align__(16) bf16 g_lemb_h[(size_t)L_SIZE * D];
__device__ __align__(16) bf16 g_lemb_l[(size_t)L_SIZE * D];
__device__ __align__(16) bf16 g_cemb_h[(size_t)C_SIZE * D];
__device__ __align__(16) bf16 g_cemb_l[(size_t)C_SIZE * D];
__device__ __align__(16) float g_msg_l[(size_t)L_SIZE * D];
__device__ __align__(16) float g_msg_c[(size_t)C_SIZE * D];
__device__ __align__(16) bf16 g_l2l_h[(size_t)L_SIZE * D];
__device__ __align__(16) bf16 g_l2l_l[(size_t)L_SIZE * D];
__device__ __align__(16) bf16 g_agl_h[(size_t)L_SIZE * D];
__device__ __align__(16) bf16 g_agl_l[(size_t)L_SIZE * D];
__device__ __align__(16) bf16 g_agc_h[(size_t)C_SIZE * D];
__device__ __align__(16) bf16 g_agc_l[(size_t)C_SIZE * D];
__device__ __align__(16) bf16 g_wimg_h[22 * 8192];
__device__ __align__(16) bf16 g_wimg_l[22 * 8192];
__device__ int   g_cnt_l[L_SIZE], g_cnt_c[C_SIZE];
__device__ int   g_off_l[L_SIZE], g_off_c[C_SIZE];
__device__ int   g_cur_l[L_SIZE], g_cur_c[C_SIZE];
__device__ int   g_adj_c[E_SIZE];
__device__ int   g_adj_l[E_SIZE];
__device__ float g_inv_l[L_SIZE], g_inv_c[C_SIZE];
__device__ int   g_bsum[96];
__device__ int   g_idx64;

// ================= helpers =================
__device__ __forceinline__ uint32_t smem_u32(const void* p) {
    uint32_t a;
    asm("{ .reg .u64 t; cvta.to.shared.u64 t, %1; cvt.u32.u64 %0, t; }" : "=r"(a) : "l"(p));
    return a;
}
__device__ __forceinline__ int swz(int off) { return off ^ ((off >> 3) & 0x70); }

__device__ __forceinline__ void split_bf(float v, unsigned short& h, unsigned short& l) {
    bf16 hb = __float2bfloat16_rn(v);
    bf16 lb = __float2bfloat16_rn(v - __bfloat162float(hb));
    h = __bfloat16_as_ushort(hb);
    l = __bfloat16_as_ushort(lb);
}

__device__ __forceinline__ void ldmx4(uint32_t* r, uint32_t addr) {
    asm volatile("ldmatrix.sync.aligned.m8n8.x4.shared.b16 {%0,%1,%2,%3}, [%4];"
                 : "=r"(r[0]), "=r"(r[1]), "=r"(r[2]), "=r"(r[3]) : "r"(addr));
}

__device__ __forceinline__ void mma16816(float (&c)[4], const uint32_t* a, const uint32_t* b) {
    asm volatile(
        "mma.sync.aligned.m16n8k16.row.col.f32.bf16.bf16.f32 "
        "{%0,%1,%2,%3}, {%4,%5,%6,%7}, {%8,%9}, {%0,%1,%2,%3};"
        : "+f"(c[0]), "+f"(c[1]), "+f"(c[2]), "+f"(c[3])
        : "r"(a[0]), "r"(a[1]), "r"(a[2]), "r"(a[3]), "r"(b[0]), "r"(b[1]));
}

__device__ __forceinline__ void cpa16(uint32_t dst, const void* src) {
    asm volatile("cp.async.cg.shared.global [%0], [%1], 16;" :: "r"(dst), "l"(src) : "memory");
}
#define CP_COMMIT() asm volatile("cp.async.commit_group;" ::: "memory")
#define CP_WAIT(n)  asm volatile("cp.async.wait_group %0;" :: "n"(n) : "memory")

// ===== SMEM maps (bytes) =====
#define M_A  2048
#define M_H  67584
#define M_W  133120
#define SMEM_MLP 231424
#define U_SL 2048
#define SMEM_UPD (2048 + 3 * 65536)

// ================= edge-index dtype handling =================
__device__ __forceinline__ int eidx(const void* p, int i, int f) {
    if (f) return (int)((const unsigned long long*)p)[i];
    return ((const int*)p)[i];
}

// L1: zero degree counters + dtype detect (block 0)
__global__ void k_zero_detect(const unsigned* p) {
    int i = blockIdx.x * 256 + threadIdx.x;        // grid 384 -> covers L+C
    if (i < L_SIZE) g_cnt_l[i] = 0;
    else g_cnt_c[i - L_SIZE] = 0;
    if (blockIdx.x == 0) {
        unsigned v = p[2 * threadIdx.x + 1];
        __shared__ int anynz;
        if (threadIdx.x == 0) anynz = 0;
        __syncthreads();
        unsigned b = __ballot_sync(0xffffffffu, v != 0u);
        if ((threadIdx.x & 31) == 0 && b) atomicExch(&anynz, 1);
        __syncthreads();
        if (threadIdx.x == 0) g_idx64 = (anynz == 0) ? 1 : 0;
    }
}
// L2
__global__ void k_hist(const void* lp, const void* cp) {
    int e = blockIdx.x * blockDim.x + threadIdx.x;
    int f = g_idx64;
    atomicAdd(&g_cnt_l[eidx(lp, e, f)], 1);
    atomicAdd(&g_cnt_c[eidx(cp, e, f)], 1);
}
// L3: merged block sums: blocks 0..63 -> cnt_l, 64..95 -> cnt_c
__global__ void k_bsum_all() {
    __shared__ int sh[256];
    const int* cnt = (blockIdx.x < 64) ? g_cnt_l : g_cnt_c;
    int rel = (blockIdx.x < 64) ? blockIdx.x : blockIdx.x - 64;
    int base = rel * 1024 + threadIdx.x;
    int s = 0;
#pragma unroll
    for (int t = 0; t < 4; t++) s += cnt[base + t * 256];
    sh[threadIdx.x] = s;
    __syncthreads();
    for (int o = 128; o > 0; o >>= 1) {
        if (threadIdx.x < o) sh[threadIdx.x] += sh[threadIdx.x + o];
        __syncthreads();
    }
    if (threadIdx.x == 0) g_bsum[blockIdx.x] = sh[0];
}
// L4: blocks 0..95 scan+write offsets; blocks 96..117 weight-image prep
__global__ void k_scanw_wprep(const float* w0, const float* w1, const float* w2,
                              const float* w3, const float* w4, const float* w5,
                              const float* wcu, const float* wlu) {
    int tid = threadIdx.x;
    if (blockIdx.x < 96) {
        __shared__ int sh[256];
        __shared__ int sb[64];
        int isl = blockIdx.x < 64;
        int lo = isl ? 0 : 64;
        int rel = blockIdx.x - lo;
        const int* cnt = isl ? g_cnt_l : g_cnt_c;
        int* off = isl ? g_off_l : g_off_c;
        int* cur = isl ? g_cur_l : g_cur_c;

        if (tid < 64) sb[tid] = (tid < rel) ? g_bsum[lo + tid] : 0;
        __syncthreads();
        for (int o = 32; o > 0; o >>= 1) {
            if (tid < o) sb[tid] += sb[tid + o];
            __syncthreads();
        }
        int base = sb[0];
        int base4 = rel * 1024 + tid * 4;
        int4 v = *(const int4*)(cnt + base4);
        int tsum = v.x + v.y + v.z + v.w;
        sh[tid] = tsum;
        __syncthreads();
        for (int o = 1; o < 256; o <<= 1) {
            int t = (tid >= o) ? sh[tid - o] : 0;
            __syncthreads();
            sh[tid] += t;
            __syncthreads();
        }
        int e = base + sh[tid] - tsum;
        off[base4 + 0] = e; cur[base4 + 0] = e; e += v.x;
        off[base4 + 1] = e; cur[base4 + 1] = e; e += v.y;
        off[base4 + 2] = e; cur[base4 + 2] = e; e += v.z;
        off[base4 + 3] = e; cur[base4 + 3] = e;
    } else {
        int half = blockIdx.x - 96;
        const float* W;
        int k0;
        if (half < 12) {
            const float* ws[6] = {w0, w1, w2, w3, w4, w5};
            W = ws[half >> 1];
            k0 = (half & 1) * 64;
        } else if (half < 16) {
            W = wcu; k0 = (half - 12) * 64;
        } else {
            W = wlu; k0 = (half - 16) * 64;
        }
        bf16* oh = g_wimg_h + (size_t)half * 8192;
        bf16* ol = g_wimg_l + (size_t)half * 8192;
        for (int idx = tid; idx < 8192; idx += 256) {
            int n = idx >> 6, k = idx & 63;
            float v = W[(size_t)(k0 + k) * 128 + n];
            unsigned short h, l;
            split_bf(v, h, l);
            int sw = swz(n * 128 + k * 2);
            *(unsigned short*)((char*)oh + sw) = h;
            *(unsigned short*)((char*)ol + sw) = l;
        }
    }
}
// L5: blocks 0..1023 CSR fill; 1024..1279 inv; 1280..7423 embedding init
__global__ void k_fill_inv_init(const void* lp, const void* cp,
                                const float* __restrict__ l_init,
                                const float* __restrict__ c_init) {
    int bid = blockIdx.x, tid = threadIdx.x;
    if (bid < 1024) {
        int e = bid * 256 + tid;
        int f = g_idx64;
        int li = eidx(lp, e, f);
        int ci = eidx(cp, e, f);
        g_adj_c[atomicAdd(&g_cur_c[ci], 1)] = li;
        g_adj_l[atomicAdd(&g_cur_l[li], 1)] = ci;
    } else if (bid < 1280) {
        int i = (bid - 1024) * 256 + tid;
        if (i < L_SIZE) { int c = g_cnt_l[i]; g_inv_l[i] = c ? rsqrtf((float)c) : 0.0f; }
        if (i < C_SIZE) { int c = g_cnt_c[i]; g_inv_c[i] = c ? rsqrtf((float)c) : 0.0f; }
    } else {
        int i = (bid - 1280) * 256 + tid;
        bf16 *dh, *dl;
        const float* init;
        int rel;
        if (i < L_SIZE * 16) { dh = g_lemb_h; dl = g_lemb_l; init = l_init; rel = i; }
        else { dh = g_cemb_h; dl = g_cemb_l; init = c_init; rel = i - L_SIZE * 16; }
        int c8 = (rel & 15) * 8;
        size_t base = (size_t)(rel >> 4) * 128 + c8;
        unsigned short hh[8], ll[8];
#pragma unroll
        for (int j = 0; j < 8; j++) split_bf(init[c8 + j], hh[j], ll[j]);
        uint4 H, L;
        H.x = hh[0] | ((uint32_t)hh[1] << 16); H.y = hh[2] | ((uint32_t)hh[3] << 16);
        H.z = hh[4] | ((uint32_t)hh[5] << 16); H.w = hh[6] | ((uint32_t)hh[7] << 16);
        L.x = ll[0] | ((uint32_t)ll[1] << 16); L.y = ll[2] | ((uint32_t)ll[3] << 16);
        L.z = ll[4] | ((uint32_t)ll[5] << 16); L.w = ll[6] | ((uint32_t)ll[7] << 16);
        *(uint4*)(dh + base) = H;
        *(uint4*)(dl + base) = L;
    }
}

// ================= async tile fills (strided by DMA-thread count) =================
__device__ __forceinline__ void issue_A_full(uint32_t a_base, const bf16* __restrict__ Xh,
                                             const bf16* __restrict__ Xl, size_t rowbase,
                                             int t, int stride) {
    for (int i = t; i < 2048; i += stride) {
        int row = i >> 4, u = i & 15;
        int half = u >> 3, uu = u & 7;
        size_t goff = (rowbase + row) * 128 + u * 8;
        uint32_t d = a_base + half * 32768 + swz(row * 128 + uu * 16);
        cpa16(d, Xh + goff);
        cpa16(d + 16384, Xl + goff);
    }
}
__device__ __forceinline__ void issue_W(uint32_t slot, int wimg, int t, int stride) {
    const uint4* sh = (const uint4*)(g_wimg_h + (size_t)wimg * 8192);
    const uint4* sl = (const uint4*)(g_wimg_l + (size_t)wimg * 8192);
    for (int i = t; i < 1024; i += stride) {
        cpa16(slot + i * 16, sh + i);
        cpa16(slot + 16384 + i * 16, sl + i);
    }
}
__device__ __forceinline__ void issue_half(uint32_t slot, const bf16* __restrict__ Sh,
                                           const bf16* __restrict__ Sl, size_t rowbase,
                                           int k64, int wimg, int t, int stride) {
    for (int i = t; i < 1024; i += stride) {
        int row = i >> 3, uu = i & 7;
        size_t goff = (rowbase + row) * 128 + k64 * 64 + uu * 8;
        uint32_t d = slot + swz(row * 128 + uu * 16);
        cpa16(d, Sh + goff);
        cpa16(d + 16384, Sl + goff);
        cpa16(slot + 32768 + i * 16, (const uint4*)(g_wimg_h + (size_t)wimg * 8192) + i);
        cpa16(slot + 49152 + i * 16, (const uint4*)(g_wimg_l + (size_t)wimg * 8192) + i);
    }
}

// ================= warp GEMM over one K=64 half (3-term hi/lo split) =================
__device__ __forceinline__ void warp_mma_k64(float (&acc)[16][4], uint32_t a_base,
                                             uint32_t w_base, int lane, int wid, int rxor) {
    const int wrow0 = (wid >> 1) * 32;
    const int nbase = (wid & 1) * 64;
#pragma unroll
    for (int kc = 0; kc < 4; kc++) {
        int kb = kc * 32;
        uint32_t ah[8], al[8];
#pragma unroll
        for (int mt = 0; mt < 2; mt++) {
            int arow = (wrow0 + mt * 16 + (lane & 15)) ^ rxor;
            int acol = kb + ((lane >> 4) << 4);
            uint32_t aaddr = a_base + swz(arow * 128 + acol);
            ldmx4(ah + mt * 4, aaddr);
            ldmx4(al + mt * 4, aaddr + 16384);
        }
        int brow = (lane & 7) + ((lane >> 4) & 1) * 8;
        int bcol = kb + (((lane >> 3) & 1) << 4);
        uint32_t bh[16], bl[16];
#pragma unroll
        for (int gg = 0; gg < 4; gg++) {
            uint32_t baddr = w_base + swz((nbase + gg * 16 + brow) * 128 + bcol);
            ldmx4(bh + gg * 4, baddr);
            ldmx4(bl + gg * 4, baddr + 16384);
        }
#pragma unroll
        for (int term = 0; term < 3; term++) {
            const uint32_t* A = (term == 2) ? al : ah;
            const uint32_t* B = (term == 1) ? bl : bh;
#pragma unroll
            for (int mt = 0; mt < 2; mt++)
#pragma unroll
                for (int t = 0; t < 8; t++)
                    mma16816(acc[mt * 8 + t], A + mt * 4, B + (t >> 1) * 4 + (t & 1) * 2);
        }
    }
}

// fragment -> relu/bias -> split -> H region
__device__ __forceinline__ void store_H(char* hbase, float (&acc)[16][4],
                                        const float* __restrict__ b1s, int lane, int wid) {
    const int wrow0 = (wid >> 1) * 32;
    const int nbase = (wid & 1) * 64;
    int g = lane >> 2, tig = lane & 3;
#pragma unroll
    for (int mt = 0; mt < 2; mt++)
#pragma unroll
        for (int nt = 0; nt < 8; nt++) {
            int n = nbase + nt * 8 + 2 * tig;
            int half = n >> 6, kk = n & 63;
            float bz0 = b1s[n], bz1 = b1s[n + 1];
            const float* a = acc[mt * 8 + nt];
            int r0 = wrow0 + mt * 16 + g, r1 = r0 + 8;
            float v00 = fmaxf(a[0] + bz0, 0.0f), v01 = fmaxf(a[1] + bz1, 0.0f);
            float v10 = fmaxf(a[2] + bz0, 0.0f), v11 = fmaxf(a[3] + bz1, 0.0f);
            unsigned short h00, l00, h01, l01, h10, l10, h11, l11;
            split_bf(v00, h00, l00); split_bf(v01, h01, l01);
            split_bf(v10, h10, l10); split_bf(v11, h11, l11);
            char* dh = hbase + half * 32768;
            char* dl = dh + 16384;
            int sw0 = swz(r0 * 128 + kk * 2), sw1 = swz(r1 * 128 + kk * 2);
            *(uint32_t*)(dh + sw0) = h00 | ((uint32_t)h01 << 16);
            *(uint32_t*)(dl + sw0) = l00 | ((uint32_t)l01 << 16);
            *(uint32_t*)(dh + sw1) = h10 | ((uint32_t)h11 << 16);
            *(uint32_t*)(dl + sw1) = l10 | ((uint32_t)l11 << 16);
        }
}

// fragment -> bias -> col-rotated fp32 stage (stride 128, col' = (col + 4*row) & 127)
__device__ __forceinline__ void acc_to_stage(float* __restrict__ stage, float (&acc)[16][4],
                                             const float* __restrict__ bs, int lane, int wid) {
    const int wrow0 = (wid >> 1) * 32;
    const int nbase = (wid & 1) * 64;
    int g = lane >> 2, tig = lane & 3;
#pragma unroll
    for (int mt = 0; mt < 2; mt++)
#pragma unroll
        for (int nt = 0; nt < 8; nt++) {
            int n = nbase + nt * 8 + 2 * tig;
            float bz0 = bs[n], bz1 = bs[n + 1];
            const float* a = acc[mt * 8 + nt];
            int r0 = wrow0 + mt * 16 + g, r1 = r0 + 8;
            int c0 = (n + 4 * r0) & 127, c1 = (n + 4 * r1) & 127;
            *(float2*)(stage + r0 * 128 + c0) = make_float2(a[0] + bz0, a[1] + bz1);
            *(float2*)(stage + r1 * 128 + c1) = make_float2(a[2] + bz0, a[3] + bz1);
        }
}

// staged epilogue: col-rotated smem fp32 -> gmem (call with tid < 256 only)
__device__ __forceinline__ void epilogue_writer(
    const float* __restrict__ stage, size_t rowbase,
    const float* __restrict__ inv, float* __restrict__ outf,
    bf16* __restrict__ outh, bf16* __restrict__ outl, int tid) {
    int r = tid >> 1, h = tid & 1;
    size_t grow = rowbase + r;
    const float* srow = stage + r * 128;
    int rot = 4 * r;
    if (outf) {
        float sc = inv ? inv[grow] : 1.0f;
        float4* of = (float4*)(outf + grow * 128 + h * 64);
#pragma unroll
        for (int u = 0; u < 16; u++) {
            float4 v = *(const float4*)(srow + ((h * 64 + u * 4 + rot) & 127));
            v.x *= sc; v.y *= sc; v.z *= sc; v.w *= sc;
            of[u] = v;
        }
    }
    if (outh) {
        uint4* oh = (uint4*)(outh + grow * 128 + h * 64);
        uint4* ol = (uint4*)(outl + grow * 128 + h * 64);
#pragma unroll
        for (int u = 0; u < 8; u++) {
            float4 a = *(const float4*)(srow + ((h * 64 + u * 8 + rot) & 127));
            float4 b = *(const float4*)(srow + ((h * 64 + u * 8 + 4 + rot) & 127));
            unsigned short hh[8], ll[8];
            split_bf(a.x, hh[0], ll[0]); split_bf(a.y, hh[1], ll[1]);
            split_bf(a.z, hh[2], ll[2]); split_bf(a.w, hh[3], ll[3]);
            split_bf(b.x, hh[4], ll[4]); split_bf(b.y, hh[5], ll[5]);
            split_bf(b.z, hh[6], ll[6]); split_bf(b.w, hh[7], ll[7]);
            uint4 H, L;
            H.x = hh[0] | ((uint32_t)hh[1] << 16); H.y = hh[2] | ((uint32_t)hh[3] << 16);
            H.z = hh[4] | ((uint32_t)hh[5] << 16); H.w = hh[6] | ((uint32_t)hh[7] << 16);
            L.x = ll[0] | ((uint32_t)ll[1] << 16); L.y = ll[2] | ((uint32_t)ll[3] << 16);
            L.z = ll[4] | ((uint32_t)ll[5] << 16); L.w = ll[6] | ((uint32_t)ll[7] << 16);
            oh[u] = H;
            ol[u] = L;
        }
    }
}

#define ZERO_ACC(acc) do {                       \
    _Pragma("unroll")                            \
    for (int t_ = 0; t_ < 16; t_++)              \
        _Pragma("unroll")                        \
        for (int j_ = 0; j_ < 4; j_++) (acc)[t_][j_] = 0.0f; } while (0)

// ================= mega MLP kernel (384 threads: 8 compute + 4 DMA warps) =================
__global__ __launch_bounds__(384, 1) void k_mlp_all(
    const bf16* __restrict__ lemb_h, const bf16* __restrict__ lemb_l,
    const bf16* __restrict__ cemb_h, const bf16* __restrict__ cemb_l,
    const float* __restrict__ b_l2c1, const float* __restrict__ b_l2c2,
    const float* __restrict__ b_c2l1, const float* __restrict__ b_c2l2,
    const float* __restrict__ b_l2l1, const float* __restrict__ b_l2l2,
    const float* __restrict__ inv_l, const float* __restrict__ inv_c,
    float* __restrict__ msg_l, float* __restrict__ msg_c,
    bf16* __restrict__ l2l_h, bf16* __restrict__ l2l_l) {
    extern __shared__ __align__(1024) char sm[];
    uint32_t smem_base = smem_u32(sm);
    float* bs = (float*)sm;
    float* stage = (float*)(sm + M_H);
    int tid = threadIdx.x, wid = tid >> 5, lane = tid & 31;
    bool dma = tid >= 256;
    int dtid = tid - 256;
    int bid = blockIdx.x;
    bool isL = bid < NL_CTA;
    size_t rowbase = isL ? (size_t)bid * 128 : (size_t)(bid - NL_CTA) * 128;
    const bf16* Xh = isL ? lemb_h : cemb_h;
    const bf16* Xl = isL ? lemb_l : cemb_l;
    int nstep = isL ? 8 : 4;

    uint32_t AB = smem_base + M_A, HB = smem_base + M_H, WB = smem_base + M_W;

    if (dma) {
        // bias staging
        if (isL) {
            for (int i = dtid; i < 512; i += 128) {
                float v;
                if (i < 128) v = b_l2c1[i];
                else if (i < 256) v = b_l2c2[i - 128];
                else if (i < 384) v = b_l2l1[i - 256];
                else v = b_l2l2[i - 384];
                bs[i] = v;
            }
        } else {
            bs[dtid] = b_c2l1[dtid];
            bs[dtid + 128] = b_c2l2[dtid];
        }
        // prologue: A + first 3 W slots
        issue_A_full(AB, Xh, Xl, rowbase, dtid, 128);
        issue_W(WB, isL ? 0 : 4, dtid, 128);
        CP_COMMIT();
        issue_W(WB + 32768, isL ? 1 : 5, dtid, 128);
        CP_COMMIT();
        issue_W(WB + 65536, isL ? 2 : 6, dtid, 128);
        CP_COMMIT();
    }

    float acc[16][4];
    ZERO_ACC(acc);

#pragma unroll 1
    for (int j = 0; j < nstep; j++) {
        if (dma) {
            if (j == 0) CP_WAIT(2);
            else if (j == nstep - 1) CP_WAIT(0);
            else CP_WAIT(1);
        }
        __syncthreads();
        if (dma && j >= 1 && j + 2 < nstep) {
            int im = j + 2;
            int wimg = isL ? (im < 4 ? im : im + 4) : (4 + im);
            issue_W(WB + ((im % 3) * 32768), wimg, dtid, 128);
            CP_COMMIT();
        }
        int ph = j >> 1;
        bool p2 = (ph & 1) != 0;
        if (!dma) {
            uint32_t abase = (p2 ? HB : AB) + (j & 1) * 32768;
            int rxor = (isL && ph == 2) ? 1 : 0;
            warp_mma_k64(acc, abase, WB + (j % 3) * 32768, lane, wid, rxor);
        }
        if (j & 1) {
            if (!p2) {
                if (!dma) {
                    store_H(sm + M_H, acc, bs + ((ph >> 1) * 256), lane, wid);
                    ZERO_ACC(acc);
                }
            } else {
                __syncthreads();
                if (!dma) acc_to_stage(stage, acc, bs + 128 + ((ph >> 1) * 256), lane, wid);
                __syncthreads();
                if (!dma) {
                    if (!isL)
                        epilogue_writer(stage, rowbase, inv_c, msg_c, nullptr, nullptr, tid);
                    else if (ph == 1)
                        epilogue_writer(stage, rowbase, inv_l, msg_l, nullptr, nullptr, tid);
                    else
                        epilogue_writer(stage, rowbase, nullptr, nullptr, l2l_h, l2l_l, tid);
                    ZERO_ACC(acc);
                }
            }
        }
    }
}

// ================= mega update kernel (384 threads: 8 compute + 4 DMA warps) ==========
__global__ __launch_bounds__(384, 1) void k_upd_all(
    const bf16* __restrict__ lemb_h, const bf16* __restrict__ lemb_l,
    const bf16* __restrict__ agl_h, const bf16* __restrict__ agl_l,
    const bf16* __restrict__ l2l_h, const bf16* __restrict__ l2l_l,
    const bf16* __restrict__ cemb_h, const bf16* __restrict__ cemb_l,
    const bf16* __restrict__ agc_h, const bf16* __restrict__ agc_l,
    const float* __restrict__ b_lu, const float* __restrict__ b_cu,
    bf16* __restrict__ olemb_h, bf16* __restrict__ olemb_l,
    bf16* __restrict__ ocemb_h, bf16* __restrict__ ocemb_l,
    float* __restrict__ fo) {
    extern __shared__ __align__(1024) char sm[];
    uint32_t smem_base = smem_u32(sm);
    float* bs = (float*)sm;
    float* stage = (float*)(sm + U_SL);
    int tid = threadIdx.x, wid = tid >> 5, lane = tid & 31;
    bool dma = tid >= 256;
    int dtid = tid - 256;
    int bid = blockIdx.x;
    bool isL = bid < NL_CTA;
    size_t rowbase = isL ? (size_t)bid * 128 : (size_t)(bid - NL_CTA) * 128;
    int H = isL ? 6 : 4;
    int whalf = isL ? 16 : 12;

    const bf16* Sh[3];
    const bf16* Sl[3];
    if (isL) { Sh[0] = lemb_h; Sl[0] = lemb_l; Sh[1] = agl_h; Sl[1] = agl_l; Sh[2] = l2l_h; Sl[2] = l2l_l; }
    else { Sh[0] = cemb_h; Sl[0] = cemb_l; Sh[1] = agc_h; Sl[1] = agc_l; Sh[2] = cemb_h; Sl[2] = cemb_l; }

    if (dma) {
        bs[dtid] = isL ? b_lu[dtid] : b_cu[dtid];
#pragma unroll
        for (int s = 0; s < 3; s++) {
            int c = s >> 1;
            issue_half(smem_base + U_SL + s * 65536, Sh[c], Sl[c], rowbase, s & 1,
                       whalf + s, dtid, 128);
            CP_COMMIT();
        }
    }

    float acc[16][4];
    ZERO_ACC(acc);

#pragma unroll 1
    for (int h = 0; h < H; h++) {
        if (dma) {
            if (h == 0) CP_WAIT(2);
            else if (h == H - 1) CP_WAIT(0);
            else CP_WAIT(1);
        }
        __syncthreads();
        if (dma && h >= 1 && h + 2 < H) {
            int s = h + 2;
            int c = s >> 1;
            issue_half(smem_base + U_SL + (s % 3) * 65536, Sh[c], Sl[c], rowbase,
                       s & 1, whalf + s, dtid, 128);
            CP_COMMIT();
        }
        if (!dma) {
            uint32_t slot = smem_base + U_SL + (h % 3) * 65536;
            warp_mma_k64(acc, slot, slot + 32768, lane, wid, 0);
        }
    }
    __syncthreads();
    if (!dma) acc_to_stage(stage, acc, bs, lane, wid);
    __syncthreads();
    if (!dma) {
        if (isL) epilogue_writer(stage, rowbase, nullptr, fo, olemb_h, olemb_l, tid);
        else epilogue_writer(stage, rowbase, nullptr, nullptr, ocemb_h, ocemb_l, tid);
    }
}

// ================= merged CSR aggregation (C then L) -> hi/lo bf16 =================
__global__ void k_aggr_all(const float* __restrict__ msg_l, const float* __restrict__ msg_c) {
    int w = blockIdx.x * 8 + (threadIdx.x >> 5);
    int lane = threadIdx.x & 31;
    const float* msg;
    const int *adj, *off, *cnt;
    const float* inv;
    bf16 *outh, *outl;
    int node;
    if (w < C_SIZE) {
        node = w; msg = msg_l; adj = g_adj_c; off = g_off_c; cnt = g_cnt_c;
        inv = g_inv_c; outh = g_agc_h; outl = g_agc_l;
    } else {
        node = w - C_SIZE; msg = msg_c; adj = g_adj_l; off = g_off_l; cnt = g_cnt_l;
        inv = g_inv_l; outh = g_agl_h; outl = g_agl_l;
    }
    int o = off[node], d = cnt[node];
    float4 acc = make_float4(0.f, 0.f, 0.f, 0.f);
    float4 acc2 = make_float4(0.f, 0.f, 0.f, 0.f);
    int j = 0;
    for (; j + 2 <= d; j += 2) {
        int s0 = adj[o + j], s1 = adj[o + j + 1];
        float4 v0 = *(const float4*)(msg + (size_t)s0 * D + lane * 4);
        float4 v1 = *(const float4*)(msg + (size_t)s1 * D + lane * 4);
        acc.x += v0.x; acc.y += v0.y; acc.z += v0.z; acc.w += v0.w;
        acc2.x += v1.x; acc2.y += v1.y; acc2.z += v1.z; acc2.w += v1.w;
    }
    if (j < d) {
        int s0 = adj[o + j];
        float4 v0 = *(const float4*)(msg + (size_t)s0 * D + lane * 4);
        acc.x += v0.x; acc.y += v0.y; acc.z += v0.z; acc.w += v0.w;
    }
    acc.x += acc2.x; acc.y += acc2.y; acc.z += acc2.z; acc.w += acc2.w;
    float sc = inv[node];
    acc.x *= sc; acc.y *= sc; acc.z *= sc; acc.w *= sc;
    unsigned short hh[4], ll[4];
    split_bf(acc.x, hh[0], ll[0]); split_bf(acc.y, hh[1], ll[1]);
    split_bf(acc.z, hh[2], ll[2]); split_bf(acc.w, hh[3], ll[3]);
    uint2 Hh, Ll;
    Hh.x = hh[0] | ((uint32_t)hh[1] << 16); Hh.y = hh[2] | ((uint32_t)hh[3] << 16);
    Ll.x = ll[0] | ((uint32_t)ll[1] << 16); Ll.y = ll[2] | ((uint32_t)ll[3] << 16);
    *(uint2*)(outh + (size_t)node * D + lane * 4) = Hh;
    *(uint2*)(outl + (size_t)node * D + lane * 4) = Ll;
}

// ================= host launcher =================
extern "C" void kernel_launch(void* const* d_in, const int* in_sizes, int n_in,
                              void* d_out, int out_size) {
    const void* l_ei = d_in[0];
    const void* c_ei = d_in[1];
    const float* l_init = (const float*)d_in[2];
    const float* c_init = (const float*)d_in[3];
    const float* w_l2c1 = (const float*)d_in[4],  *b_l2c1 = (const float*)d_in[5];
    const float* w_l2c2 = (const float*)d_in[6],  *b_l2c2 = (const float*)d_in[7];
    const float* w_c2l1 = (const float*)d_in[8],  *b_c2l1 = (const float*)d_in[9];
    const float* w_c2l2 = (const float*)d_in[10], *b_c2l2 = (const float*)d_in[11];
    const float* w_l2l1 = (const float*)d_in[12], *b_l2l1 = (const float*)d_in[13];
    const float* w_l2l2 = (const float*)d_in[14], *b_l2l2 = (const float*)d_in[15];
    const float* w_cu   = (const float*)d_in[16], *b_cu   = (const float*)d_in[17];
    const float* w_lu   = (const float*)d_in[18], *b_lu   = (const float*)d_in[19];
    (void)in_sizes; (void)n_in; (void)out_size;

    bf16 *lemb_h, *lemb_l, *cemb_h, *cemb_l, *l2l_h, *l2l_l;
    bf16 *agl_h, *agl_l, *agc_h, *agc_l;
    float *msg_l, *msg_c, *inv_l, *inv_c;
    cudaGetSymbolAddress((void**)&lemb_h, g_lemb_h);
    cudaGetSymbolAddress((void**)&lemb_l, g_lemb_l);
    cudaGetSymbolAddress((void**)&cemb_h, g_cemb_h);
    cudaGetSymbolAddress((void**)&cemb_l, g_cemb_l);
    cudaGetSymbolAddress((void**)&l2l_h, g_l2l_h);
    cudaGetSymbolAddress((void**)&l2l_l, g_l2l_l);
    cudaGetSymbolAddress((void**)&agl_h, g_agl_h);
    cudaGetSymbolAddress((void**)&agl_l, g_agl_l);
    cudaGetSymbolAddress((void**)&agc_h, g_agc_h);
    cudaGetSymbolAddress((void**)&agc_l, g_agc_l);
    cudaGetSymbolAddress((void**)&msg_l, g_msg_l);
    cudaGetSymbolAddress((void**)&msg_c, g_msg_c);
    cudaGetSymbolAddress((void**)&inv_l, g_inv_l);
    cudaGetSymbolAddress((void**)&inv_c, g_inv_c);

    cudaFuncSetAttribute(k_mlp_all, cudaFuncAttributeMaxDynamicSharedMemorySize, SMEM_MLP);
    cudaFuncSetAttribute(k_upd_all, cudaFuncAttributeMaxDynamicSharedMemorySize, SMEM_UPD);

    // ---- setup: exactly 5 launches so launch #6 (profiled) is k_mlp_all ----
    k_zero_detect<<<384, 256>>>((const unsigned*)l_ei);
    k_hist<<<E_SIZE / 256, 256>>>(l_ei, c_ei);
    k_bsum_all<<<96, 256>>>();
    k_scanw_wprep<<<118, 256>>>(w_l2c1, w_l2c2, w_c2l1, w_c2l2, w_l2l1, w_l2l2, w_cu, w_lu);
    k_fill_inv_init<<<7424, 256>>>(l_ei, c_ei, l_init, c_init);

    // ---- message-passing iterations: 3 launches each ----
    for (int it = 0; it < N_ITERS; it++) {
        k_mlp_all<<<NL_CTA + NC_CTA, 384, SMEM_MLP>>>(
            lemb_h, lemb_l, cemb_h, cemb_l,
            b_l2c1, b_l2c2, b_c2l1, b_c2l2, b_l2l1, b_l2l2,
            inv_l, inv_c, msg_l, msg_c, l2l_h, l2l_l);

        k_aggr_all<<<(L_SIZE + C_SIZE) / 8, 256>>>(msg_l, msg_c);

        float* fo = (it == N_ITERS - 1) ? (float*)d_out : nullptr;
        k_upd_all<<<NL_CTA + NC_CTA, 384, SMEM_UPD>>>(
            lemb_h, lemb_l, agl_h, agl_l, l2l_h, l2l_l,
            cemb_h, cemb_l, agc_h, agc_l,
            b_lu, b_cu, lemb_h, lemb_l, cemb_h, cemb_l, fo);
    }
}

// round 11
// speedup vs baseline: 4.4064x; 2.2040x over previous
#include <cuda_runtime.h>
#include <cuda_fp16.h>
#include <cstdint>

#define L_SIZE 65536
#define C_SIZE 32768
#define E_SIZE 262144
#define D 128
#define N_ITERS 4
#define NL_CTA (L_SIZE / 128)   // 512
#define NC_CTA (C_SIZE / 128)   // 256

// ================= device scratch =================
__device__ __align__(16) __half g_lemb[(size_t)L_SIZE * D];
__device__ __align__(16) __half g_cemb[(size_t)C_SIZE * D];
__device__ __align__(16) __half g_msg_l[(size_t)L_SIZE * D];
__device__ __align__(16) __half g_msg_c[(size_t)C_SIZE * D];
__device__ __align__(16) __half g_l2l[(size_t)L_SIZE * D];
__device__ __align__(16) __half g_agl[(size_t)L_SIZE * D];
__device__ __align__(16) __half g_agc[(size_t)C_SIZE * D];
__device__ __align__(16) __half g_wimg[22 * 8192];
__device__ int   g_cnt_l[L_SIZE], g_cnt_c[C_SIZE];
__device__ int   g_off_l[L_SIZE], g_off_c[C_SIZE];
__device__ int   g_cur_l[L_SIZE], g_cur_c[C_SIZE];
__device__ int   g_adj_c[E_SIZE];
__device__ int   g_adj_l[E_SIZE];
__device__ float g_inv_l[L_SIZE], g_inv_c[C_SIZE];
__device__ int   g_bsum[96];
__device__ int   g_idx64;

// ================= helpers =================
__device__ __forceinline__ uint32_t smem_u32(const void* p) {
    uint32_t a;
    asm("{ .reg .u64 t; cvta.to.shared.u64 t, %1; cvt.u32.u64 %0, t; }" : "=r"(a) : "l"(p));
    return a;
}
__device__ __forceinline__ int swz(int off) { return off ^ ((off >> 3) & 0x70); }

__device__ __forceinline__ void ldmx4(uint32_t* r, uint32_t addr) {
    asm volatile("ldmatrix.sync.aligned.m8n8.x4.shared.b16 {%0,%1,%2,%3}, [%4];"
                 : "=r"(r[0]), "=r"(r[1]), "=r"(r[2]), "=r"(r[3]) : "r"(addr));
}

__device__ __forceinline__ void mma16816(float (&c)[4], const uint32_t* a, const uint32_t* b) {
    asm volatile(
        "mma.sync.aligned.m16n8k16.row.col.f32.f16.f16.f32 "
        "{%0,%1,%2,%3}, {%4,%5,%6,%7}, {%8,%9}, {%0,%1,%2,%3};"
        : "+f"(c[0]), "+f"(c[1]), "+f"(c[2]), "+f"(c[3])
        : "r"(a[0]), "r"(a[1]), "r"(a[2]), "r"(a[3]), "r"(b[0]), "r"(b[1]));
}

__device__ __forceinline__ void cpa16(uint32_t dst, const void* src) {
    asm volatile("cp.async.cg.shared.global [%0], [%1], 16;" :: "r"(dst), "l"(src) : "memory");
}
#define CP_COMMIT() asm volatile("cp.async.commit_group;" ::: "memory")
#define CP_WAIT(n)  asm volatile("cp.async.wait_group %0;" :: "n"(n) : "memory")

// ===== SMEM maps (bytes) =====
// MLP: bias[512f]@0; A@2048 (2x16K); H@34816 (2x16K); W-ring @67584 (3x16K). total 116736.
#define M_A  2048
#define M_H  34816
#define M_W  67584
#define SMEM_MLP 116736
// UPD: bias@0; 3 slots @2048, each 32K = [A 16K | W 16K]. total 100352 -> occ 2.
#define U_SL 2048
#define SMEM_UPD (2048 + 3 * 32768)

// ================= edge-index dtype handling =================
__device__ __forceinline__ int eidx(const void* p, int i, int f) {
    if (f) return (int)((const unsigned long long*)p)[i];
    return ((const int*)p)[i];
}

// L1: zero degree counters + dtype detect (block 0)
__global__ void k_zero_detect(const unsigned* p) {
    int i = blockIdx.x * 256 + threadIdx.x;        // grid 384 -> covers L+C
    if (i < L_SIZE) g_cnt_l[i] = 0;
    else g_cnt_c[i - L_SIZE] = 0;
    if (blockIdx.x == 0) {
        unsigned v = p[2 * threadIdx.x + 1];
        __shared__ int anynz;
        if (threadIdx.x == 0) anynz = 0;
        __syncthreads();
        unsigned b = __ballot_sync(0xffffffffu, v != 0u);
        if ((threadIdx.x & 31) == 0 && b) atomicExch(&anynz, 1);
        __syncthreads();
        if (threadIdx.x == 0) g_idx64 = (anynz == 0) ? 1 : 0;
    }
}
// L2
__global__ void k_hist(const void* lp, const void* cp) {
    int e = blockIdx.x * blockDim.x + threadIdx.x;
    int f = g_idx64;
    atomicAdd(&g_cnt_l[eidx(lp, e, f)], 1);
    atomicAdd(&g_cnt_c[eidx(cp, e, f)], 1);
}
// L3: merged block sums
__global__ void k_bsum_all() {
    __shared__ int sh[256];
    const int* cnt = (blockIdx.x < 64) ? g_cnt_l : g_cnt_c;
    int rel = (blockIdx.x < 64) ? blockIdx.x : blockIdx.x - 64;
    int base = rel * 1024 + threadIdx.x;
    int s = 0;
#pragma unroll
    for (int t = 0; t < 4; t++) s += cnt[base + t * 256];
    sh[threadIdx.x] = s;
    __syncthreads();
    for (int o = 128; o > 0; o >>= 1) {
        if (threadIdx.x < o) sh[threadIdx.x] += sh[threadIdx.x + o];
        __syncthreads();
    }
    if (threadIdx.x == 0) g_bsum[blockIdx.x] = sh[0];
}
// L4: blocks 0..95 scan+write offsets; blocks 96..117 weight-image prep (fp16)
__global__ void k_scanw_wprep(const float* w0, const float* w1, const float* w2,
                              const float* w3, const float* w4, const float* w5,
                              const float* wcu, const float* wlu) {
    int tid = threadIdx.x;
    if (blockIdx.x < 96) {
        __shared__ int sh[256];
        __shared__ int sb[64];
        int isl = blockIdx.x < 64;
        int lo = isl ? 0 : 64;
        int rel = blockIdx.x - lo;
        const int* cnt = isl ? g_cnt_l : g_cnt_c;
        int* off = isl ? g_off_l : g_off_c;
        int* cur = isl ? g_cur_l : g_cur_c;

        if (tid < 64) sb[tid] = (tid < rel) ? g_bsum[lo + tid] : 0;
        __syncthreads();
        for (int o = 32; o > 0; o >>= 1) {
            if (tid < o) sb[tid] += sb[tid + o];
            __syncthreads();
        }
        int base = sb[0];
        int base4 = rel * 1024 + tid * 4;
        int4 v = *(const int4*)(cnt + base4);
        int tsum = v.x + v.y + v.z + v.w;
        sh[tid] = tsum;
        __syncthreads();
        for (int o = 1; o < 256; o <<= 1) {
            int t = (tid >= o) ? sh[tid - o] : 0;
            __syncthreads();
            sh[tid] += t;
            __syncthreads();
        }
        int e = base + sh[tid] - tsum;
        off[base4 + 0] = e; cur[base4 + 0] = e; e += v.x;
        off[base4 + 1] = e; cur[base4 + 1] = e; e += v.y;
        off[base4 + 2] = e; cur[base4 + 2] = e; e += v.z;
        off[base4 + 3] = e; cur[base4 + 3] = e;
    } else {
        int half = blockIdx.x - 96;
        const float* W;
        int k0;
        if (half < 12) {
            const float* ws[6] = {w0, w1, w2, w3, w4, w5};
            W = ws[half >> 1];
            k0 = (half & 1) * 64;
        } else if (half < 16) {
            W = wcu; k0 = (half - 12) * 64;
        } else {
            W = wlu; k0 = (half - 16) * 64;
        }
        __half* oimg = g_wimg + (size_t)half * 8192;
        for (int idx = tid; idx < 8192; idx += 256) {
            int n = idx >> 6, k = idx & 63;
            float v = W[(size_t)(k0 + k) * 128 + n];
            int sw = swz(n * 128 + k * 2);
            *(unsigned short*)((char*)oimg + sw) =
                __half_as_ushort(__float2half_rn(v));
        }
    }
}
// L5: blocks 0..1023 CSR fill; 1024..1279 inv; 1280..7423 embedding init
__global__ void k_fill_inv_init(const void* lp, const void* cp,
                                const float* __restrict__ l_init,
                                const float* __restrict__ c_init) {
    int bid = blockIdx.x, tid = threadIdx.x;
    if (bid < 1024) {
        int e = bid * 256 + tid;
        int f = g_idx64;
        int li = eidx(lp, e, f);
        int ci = eidx(cp, e, f);
        g_adj_c[atomicAdd(&g_cur_c[ci], 1)] = li;
        g_adj_l[atomicAdd(&g_cur_l[li], 1)] = ci;
    } else if (bid < 1280) {
        int i = (bid - 1024) * 256 + tid;
        if (i < L_SIZE) { int c = g_cnt_l[i]; g_inv_l[i] = c ? rsqrtf((float)c) : 0.0f; }
        if (i < C_SIZE) { int c = g_cnt_c[i]; g_inv_c[i] = c ? rsqrtf((float)c) : 0.0f; }
    } else {
        int i = (bid - 1280) * 256 + tid;
        __half* emb;
        const float* init;
        int rel;
        if (i < L_SIZE * 16) { emb = g_lemb; init = l_init; rel = i; }
        else { emb = g_cemb; init = c_init; rel = i - L_SIZE * 16; }
        int c8 = (rel & 15) * 8;
        size_t base = (size_t)(rel >> 4) * 128 + c8;
        __half hv[8];
#pragma unroll
        for (int j = 0; j < 8; j++) hv[j] = __float2half_rn(init[c8 + j]);
        *(uint4*)(emb + base) = *(uint4*)hv;
    }
}

// ================= async tile fills =================
// full-K A tile (2 halves) from row-major fp16 gmem
__device__ __forceinline__ void issue_A_full(uint32_t a_base, const __half* __restrict__ X,
                                             size_t rowbase, int t, int stride) {
    for (int i = t; i < 2048; i += stride) {
        int row = i >> 4, u = i & 15;
        int half = u >> 3, uu = u & 7;
        cpa16(a_base + half * 16384 + swz(row * 128 + uu * 16),
              X + (rowbase + row) * 128 + u * 8);
    }
}
// one 16K W slot from pre-swizzled image
__device__ __forceinline__ void issue_W(uint32_t slot, int wimg, int t, int stride) {
    const uint4* s = (const uint4*)(g_wimg + (size_t)wimg * 8192);
    for (int i = t; i < 1024; i += stride) cpa16(slot + i * 16, s + i);
}
// one K=64 upd slot: [A 16K | W 16K]
__device__ __forceinline__ void issue_half(uint32_t slot, const __half* __restrict__ S,
                                           size_t rowbase, int k64, int wimg,
                                           int t, int stride) {
    const uint4* wsrc = (const uint4*)(g_wimg + (size_t)wimg * 8192);
    for (int i = t; i < 1024; i += stride) {
        int row = i >> 3, uu = i & 7;
        cpa16(slot + swz(row * 128 + uu * 16),
              S + (rowbase + row) * 128 + k64 * 64 + uu * 8);
        cpa16(slot + 16384 + i * 16, wsrc + i);
    }
}

// ================= warp GEMM over one K=64 half (single fp16 term) =================
// warp (wid>>1) owns rows [(wid>>1)*32,+32); (wid&1) owns cols [(wid&1)*64,+64)
__device__ __forceinline__ void warp_mma_k64(float (&acc)[16][4], uint32_t a_base,
                                             uint32_t w_base, int lane, int wid, int rxor) {
    const int wrow0 = (wid >> 1) * 32;
    const int nbase = (wid & 1) * 64;
#pragma unroll
    for (int kc = 0; kc < 4; kc++) {
        int kb = kc * 32;
        uint32_t ar[8];
#pragma unroll
        for (int mt = 0; mt < 2; mt++) {
            int arow = (wrow0 + mt * 16 + (lane & 15)) ^ rxor;
            int acol = kb + ((lane >> 4) << 4);
            ldmx4(ar + mt * 4, a_base + swz(arow * 128 + acol));
        }
        int brow = (lane & 7) + ((lane >> 4) & 1) * 8;
        int bcol = kb + (((lane >> 3) & 1) << 4);
        uint32_t br[16];
#pragma unroll
        for (int gg = 0; gg < 4; gg++)
            ldmx4(br + gg * 4, w_base + swz((nbase + gg * 16 + brow) * 128 + bcol));
#pragma unroll
        for (int mt = 0; mt < 2; mt++)
#pragma unroll
            for (int t = 0; t < 8; t++)
                mma16816(acc[mt * 8 + t], ar + mt * 4, br + (t >> 1) * 4 + (t & 1) * 2);
    }
}

// fragment -> relu/bias -> fp16 -> H region
__device__ __forceinline__ void store_H(char* hbase, float (&acc)[16][4],
                                        const float* __restrict__ b1s, int lane, int wid) {
    const int wrow0 = (wid >> 1) * 32;
    const int nbase = (wid & 1) * 64;
    int g = lane >> 2, tig = lane & 3;
#pragma unroll
    for (int mt = 0; mt < 2; mt++)
#pragma unroll
        for (int nt = 0; nt < 8; nt++) {
            int n = nbase + nt * 8 + 2 * tig;
            int half = n >> 6, kk = n & 63;
            float bz0 = b1s[n], bz1 = b1s[n + 1];
            const float* a = acc[mt * 8 + nt];
            int r0 = wrow0 + mt * 16 + g, r1 = r0 + 8;
            __half2 p0 = __floats2half2_rn(fmaxf(a[0] + bz0, 0.0f), fmaxf(a[1] + bz1, 0.0f));
            __half2 p1 = __floats2half2_rn(fmaxf(a[2] + bz0, 0.0f), fmaxf(a[3] + bz1, 0.0f));
            char* dh = hbase + half * 16384;
            *(uint32_t*)(dh + swz(r0 * 128 + kk * 2)) = *(uint32_t*)&p0;
            *(uint32_t*)(dh + swz(r1 * 128 + kk * 2)) = *(uint32_t*)&p1;
        }
}

// direct epilogue: fragments -> gmem (fp16 and/or fp32), optional per-row inv scale
__device__ __forceinline__ void epi_direct(float (&acc)[16][4], const float* __restrict__ bs,
                                           size_t rowbase, const float* __restrict__ inv,
                                           __half* __restrict__ outh,
                                           float* __restrict__ outf, int lane, int wid) {
    const int wrow0 = (wid >> 1) * 32;
    const int nbase = (wid & 1) * 64;
    int g = lane >> 2, tig = lane & 3;
#pragma unroll
    for (int mt = 0; mt < 2; mt++) {
        int r0 = wrow0 + mt * 16 + g, r1 = r0 + 8;
        float s0 = inv ? inv[rowbase + r0] : 1.0f;
        float s1 = inv ? inv[rowbase + r1] : 1.0f;
#pragma unroll
        for (int nt = 0; nt < 8; nt++) {
            int n = nbase + nt * 8 + 2 * tig;
            const float* a = acc[mt * 8 + nt];
            float v0 = (a[0] + bs[n]) * s0, v1 = (a[1] + bs[n + 1]) * s0;
            float v2 = (a[2] + bs[n]) * s1, v3 = (a[3] + bs[n + 1]) * s1;
            if (outh) {
                __half2 p0 = __floats2half2_rn(v0, v1);
                __half2 p1 = __floats2half2_rn(v2, v3);
                *(__half2*)(outh + (rowbase + r0) * 128 + n) = p0;
                *(__half2*)(outh + (rowbase + r1) * 128 + n) = p1;
            }
            if (outf) {
                *(float2*)(outf + (rowbase + r0) * 128 + n) = make_float2(v0, v1);
                *(float2*)(outf + (rowbase + r1) * 128 + n) = make_float2(v2, v3);
            }
        }
    }
}

#define ZERO_ACC(acc) do {                       \
    _Pragma("unroll")                            \
    for (int t_ = 0; t_ < 16; t_++)              \
        _Pragma("unroll")                        \
        for (int j_ = 0; j_ < 4; j_++) (acc)[t_][j_] = 0.0f; } while (0)

// ================= mega MLP kernel =================
__global__ __launch_bounds__(256, 1) void k_mlp_all(
    const __half* __restrict__ lemb, const __half* __restrict__ cemb,
    const float* __restrict__ b_l2c1, const float* __restrict__ b_l2c2,
    const float* __restrict__ b_c2l1, const float* __restrict__ b_c2l2,
    const float* __restrict__ b_l2l1, const float* __restrict__ b_l2l2,
    const float* __restrict__ inv_l, const float* __restrict__ inv_c,
    __half* __restrict__ msg_l, __half* __restrict__ msg_c,
    __half* __restrict__ l2l) {
    extern __shared__ __align__(1024) char sm[];
    uint32_t smem_base = smem_u32(sm);
    float* bs = (float*)sm;
    int tid = threadIdx.x, wid = tid >> 5, lane = tid & 31;
    int bid = blockIdx.x;
    bool isL = bid < NL_CTA;
    size_t rowbase = isL ? (size_t)bid * 128 : (size_t)(bid - NL_CTA) * 128;
    const __half* X = isL ? lemb : cemb;
    int nstep = isL ? 8 : 4;

    if (isL) {
        for (int i = tid; i < 512; i += 256) {
            float v;
            if (i < 128) v = b_l2c1[i];
            else if (i < 256) v = b_l2c2[i - 128];
            else if (i < 384) v = b_l2l1[i - 256];
            else v = b_l2l2[i - 384];
            bs[i] = v;
        }
    } else {
        bs[tid] = (tid < 128) ? b_c2l1[tid] : b_c2l2[tid - 128];
    }

    uint32_t AB = smem_base + M_A, HB = smem_base + M_H, WB = smem_base + M_W;
    issue_A_full(AB, X, rowbase, tid, 256);
    issue_W(WB, isL ? 0 : 4, tid, 256);
    CP_COMMIT();
    issue_W(WB + 16384, isL ? 1 : 5, tid, 256);
    CP_COMMIT();
    issue_W(WB + 32768, isL ? 2 : 6, tid, 256);
    CP_COMMIT();

    float acc[16][4];
    ZERO_ACC(acc);

#pragma unroll 1
    for (int j = 0; j < nstep; j++) {
        if (j == 0) CP_WAIT(2);
        else if (j == nstep - 1) CP_WAIT(0);
        else CP_WAIT(1);
        __syncthreads();
        if (j >= 1 && j + 2 < nstep) {
            int im = j + 2;
            int wimg = isL ? (im < 4 ? im : im + 4) : (4 + im);
            issue_W(WB + (im % 3) * 16384, wimg, tid, 256);
            CP_COMMIT();
        }
        int ph = j >> 1;
        bool p2 = (ph & 1) != 0;
        uint32_t abase = (p2 ? HB : AB) + (j & 1) * 16384;
        int rxor = (isL && ph == 2) ? 1 : 0;
        warp_mma_k64(acc, abase, WB + (j % 3) * 16384, lane, wid, rxor);

        if (j & 1) {
            if (!p2) {
                store_H(sm + M_H, acc, bs + ((ph >> 1) * 256), lane, wid);
            } else {
                const float* b2 = bs + 128 + ((ph >> 1) * 256);
                if (!isL)
                    epi_direct(acc, b2, rowbase, inv_c, msg_c, nullptr, lane, wid);
                else if (ph == 1)
                    epi_direct(acc, b2, rowbase, inv_l, msg_l, nullptr, lane, wid);
                else
                    epi_direct(acc, b2, rowbase, nullptr, l2l, nullptr, lane, wid);
            }
            ZERO_ACC(acc);
        }
    }
}

// ================= mega update kernel (occ 2) =================
__global__ __launch_bounds__(256, 2) void k_upd_all(
    const __half* __restrict__ lemb, const __half* __restrict__ agl,
    const __half* __restrict__ l2l,
    const __half* __restrict__ cemb, const __half* __restrict__ agc,
    const float* __restrict__ b_lu, const float* __restrict__ b_cu,
    __half* __restrict__ olemb, __half* __restrict__ ocemb,
    float* __restrict__ fo) {
    extern __shared__ __align__(1024) char sm[];
    uint32_t smem_base = smem_u32(sm);
    float* bs = (float*)sm;
    int tid = threadIdx.x, wid = tid >> 5, lane = tid & 31;
    int bid = blockIdx.x;
    bool isL = bid < NL_CTA;
    size_t rowbase = isL ? (size_t)bid * 128 : (size_t)(bid - NL_CTA) * 128;
    int H = isL ? 6 : 4;
    int whalf = isL ? 16 : 12;

    if (tid < 128) bs[tid] = isL ? b_lu[tid] : b_cu[tid];

    const __half* S[3];
    if (isL) { S[0] = lemb; S[1] = agl; S[2] = l2l; }
    else { S[0] = cemb; S[1] = agc; S[2] = cemb; }

#pragma unroll
    for (int s = 0; s < 3; s++) {
        issue_half(smem_base + U_SL + s * 32768, S[s >> 1], rowbase, s & 1,
                   whalf + s, tid, 256);
        CP_COMMIT();
    }

    float acc[16][4];
    ZERO_ACC(acc);

#pragma unroll 1
    for (int h = 0; h < H; h++) {
        if (h == 0) CP_WAIT(2);
        else if (h == H - 1) CP_WAIT(0);
        else CP_WAIT(1);
        __syncthreads();
        if (h >= 1 && h + 2 < H) {
            int s = h + 2;
            issue_half(smem_base + U_SL + (s % 3) * 32768, S[s >> 1], rowbase,
                       s & 1, whalf + s, tid, 256);
            CP_COMMIT();
        }
        uint32_t slot = smem_base + U_SL + (h % 3) * 32768;
        warp_mma_k64(acc, slot, slot + 16384, lane, wid, 0);
    }

    if (isL) epi_direct(acc, bs, rowbase, nullptr, olemb, fo, lane, wid);
    else epi_direct(acc, bs, rowbase, nullptr, ocemb, nullptr, lane, wid);
}

// ================= merged CSR aggregation -> fp16 =================
__global__ void k_aggr_all(const __half* __restrict__ msg_l, const __half* __restrict__ msg_c) {
    int w = blockIdx.x * 8 + (threadIdx.x >> 5);
    int lane = threadIdx.x & 31;
    const __half* msg;
    const int *adj, *off, *cnt;
    const float* inv;
    __half* out;
    int node;
    if (w < C_SIZE) {
        node = w; msg = msg_l; adj = g_adj_c; off = g_off_c; cnt = g_cnt_c;
        inv = g_inv_c; out = g_agc;
    } else {
        node = w - C_SIZE; msg = msg_c; adj = g_adj_l; off = g_off_l; cnt = g_cnt_l;
        inv = g_inv_l; out = g_agl;
    }
    int o = off[node], d = cnt[node];
    float4 acc = make_float4(0.f, 0.f, 0.f, 0.f);
    float4 acc2 = make_float4(0.f, 0.f, 0.f, 0.f);
    int j = 0;
    for (; j + 2 <= d; j += 2) {
        int s0 = adj[o + j], s1 = adj[o + j + 1];
        uint2 r0 = *(const uint2*)(msg + (size_t)s0 * D + lane * 4);
        uint2 r1 = *(const uint2*)(msg + (size_t)s1 * D + lane * 4);
        float2 a0 = __half22float2(*(__half2*)&r0.x);
        float2 a1 = __half22float2(*(__half2*)&r0.y);
        float2 b0 = __half22float2(*(__half2*)&r1.x);
        float2 b1 = __half22float2(*(__half2*)&r1.y);
        acc.x += a0.x; acc.y += a0.y; acc.z += a1.x; acc.w += a1.y;
        acc2.x += b0.x; acc2.y += b0.y; acc2.z += b1.x; acc2.w += b1.y;
    }
    if (j < d) {
        int s0 = adj[o + j];
        uint2 r0 = *(const uint2*)(msg + (size_t)s0 * D + lane * 4);
        float2 a0 = __half22float2(*(__half2*)&r0.x);
        float2 a1 = __half22float2(*(__half2*)&r0.y);
        acc.x += a0.x; acc.y += a0.y; acc.z += a1.x; acc.w += a1.y;
    }
    acc.x += acc2.x; acc.y += acc2.y; acc.z += acc2.z; acc.w += acc2.w;
    float sc = inv[node];
    __half2 p0 = __floats2half2_rn(acc.x * sc, acc.y * sc);
    __half2 p1 = __floats2half2_rn(acc.z * sc, acc.w * sc);
    uint2 res;
    res.x = *(uint32_t*)&p0;
    res.y = *(uint32_t*)&p1;
    *(uint2*)(out + (size_t)node * D + lane * 4) = res;
}

// ================= host launcher =================
extern "C" void kernel_launch(void* const* d_in, const int* in_sizes, int n_in,
                              void* d_out, int out_size) {
    const void* l_ei = d_in[0];
    const void* c_ei = d_in[1];
    const float* l_init = (const float*)d_in[2];
    const float* c_init = (const float*)d_in[3];
    const float* w_l2c1 = (const float*)d_in[4],  *b_l2c1 = (const float*)d_in[5];
    const float* w_l2c2 = (const float*)d_in[6],  *b_l2c2 = (const float*)d_in[7];
    const float* w_c2l1 = (const float*)d_in[8],  *b_c2l1 = (const float*)d_in[9];
    const float* w_c2l2 = (const float*)d_in[10], *b_c2l2 = (const float*)d_in[11];
    const float* w_l2l1 = (const float*)d_in[12], *b_l2l1 = (const float*)d_in[13];
    const float* w_l2l2 = (const float*)d_in[14], *b_l2l2 = (const float*)d_in[15];
    const float* w_cu   = (const float*)d_in[16], *b_cu   = (const float*)d_in[17];
    const float* w_lu   = (const float*)d_in[18], *b_lu   = (const float*)d_in[19];
    (void)in_sizes; (void)n_in; (void)out_size;

    __half *lemb, *cemb, *l2l, *agl, *agc, *msg_l, *msg_c;
    float *inv_l, *inv_c;
    cudaGetSymbolAddress((void**)&lemb, g_lemb);
    cudaGetSymbolAddress((void**)&cemb, g_cemb);
    cudaGetSymbolAddress((void**)&l2l, g_l2l);
    cudaGetSymbolAddress((void**)&agl, g_agl);
    cudaGetSymbolAddress((void**)&agc, g_agc);
    cudaGetSymbolAddress((void**)&msg_l, g_msg_l);
    cudaGetSymbolAddress((void**)&msg_c, g_msg_c);
    cudaGetSymbolAddress((void**)&inv_l, g_inv_l);
    cudaGetSymbolAddress((void**)&inv_c, g_inv_c);

    cudaFuncSetAttribute(k_mlp_all, cudaFuncAttributeMaxDynamicSharedMemorySize, SMEM_MLP);
    cudaFuncSetAttribute(k_upd_all, cudaFuncAttributeMaxDynamicSharedMemorySize, SMEM_UPD);

    // ---- setup: 5 launches ----
    k_zero_detect<<<384, 256>>>((const unsigned*)l_ei);
    k_hist<<<E_SIZE / 256, 256>>>(l_ei, c_ei);
    k_bsum_all<<<96, 256>>>();
    k_scanw_wprep<<<118, 256>>>(w_l2c1, w_l2c2, w_c2l1, w_c2l2, w_l2l1, w_l2l2, w_cu, w_lu);
    k_fill_inv_init<<<7424, 256>>>(l_ei, c_ei, l_init, c_init);

    // ---- message-passing iterations: 3 launches each ----
    for (int it = 0; it < N_ITERS; it++) {
        k_mlp_all<<<NL_CTA + NC_CTA, 256, SMEM_MLP>>>(
            lemb, cemb,
            b_l2c1, b_l2c2, b_c2l1, b_c2l2, b_l2l1, b_l2l2,
            inv_l, inv_c, msg_l, msg_c, l2l);

        k_aggr_all<<<(L_SIZE + C_SIZE) / 8, 256>>>(msg_l, msg_c);

        float* fo = (it == N_ITERS - 1) ? (float*)d_out : nullptr;
        k_upd_all<<<NL_CTA + NC_CTA, 256, SMEM_UPD>>>(
            lemb, agl, l2l, cemb, agc,
            b_lu, b_cu, lemb, cemb, fo);
    }
}